// round 5
// baseline (speedup 1.0000x reference)
#include <cuda_runtime.h>
#include <cstdint>

// Problem constants
#define BB 2
#define HH 256
#define WW 256
#define CC 256
#define WS 8
#define SHIFT 4
#define NH 8
#define HD 32
#define OUTC 256
#define NWIN 1024      // (H/WS)*(W/WS)
#define PP 64          // WS*WS
#define MROWS 131072   // B*NWIN*PP per stream

// Scratch (device globals; no runtime allocation allowed)
// qkv layout: [stream][qkv][b][win][head][p][d]
__device__ float g_qkv[2u*3u*BB*NWIN*NH*PP*HD];        // 201,326,592 floats
// attn out layout: [stream][b][win][p][C]  (C = head*32+d)
__device__ float g_attn[2u*BB*NWIN*PP*CC];             // 67,108,864 floats
// bias table: [stream][head][p][q]
__device__ float g_bias[2*NH*PP*PP];                   // 65,536 floats

// ---------------------------------------------------------------------------
// Kernel 0: bias table from rel (NH,15,15)
// ---------------------------------------------------------------------------
__global__ void bias_kernel(const float* __restrict__ rel1,
                            const float* __restrict__ rel2)
{
    int idx = blockIdx.x * blockDim.x + threadIdx.x;   // 0 .. 65535
    int s    = idx >> 15;
    int head = (idx >> 12) & 7;
    int p    = (idx >> 6) & 63;
    int q    = idx & 63;
    const float* rel = s ? rel2 : rel1;
    int a = (p >> 3) - (q >> 3) + 7;
    int b = (p & 7) - (q & 7) + 7;
    g_bias[idx] = rel[head * 225 + a * 15 + b];
}

// ---------------------------------------------------------------------------
// Kernel 1: QKV GEMM with fused roll + window gather.
// A: gathered emb rows (M=131072, K=256)   B: Wqkv (256 x 768)
// 128x128x8 tiling, 256 threads, 8x8 register tiles.
// ---------------------------------------------------------------------------
__global__ __launch_bounds__(256)
void qkv_gemm(const float* __restrict__ emb1, const float* __restrict__ emb2,
              const float* __restrict__ Wqkv1, const float* __restrict__ bqkv1,
              const float* __restrict__ Wqkv2, const float* __restrict__ bqkv2)
{
    const int s = blockIdx.z;
    const float* __restrict__ emb = s ? emb2 : emb1;
    const float* __restrict__ Wq  = s ? Wqkv2 : Wqkv1;
    const float* __restrict__ bq  = s ? bqkv2 : bqkv1;

    __shared__ float As[8][128];   // transposed A tile
    __shared__ float Bs[8][128];

    const int tid      = threadIdx.x;
    const int rowBlock = blockIdx.y;   // 0..1023
    const int colBlock = blockIdx.x;   // 0..5

    // A-tile loader mapping: one float4 per thread per k-iter
    const int arow  = tid >> 1;          // 0..127
    const int apart = (tid & 1) * 4;     // 0 or 4
    const int R     = rowBlock * 128 + arow;
    {
        // decode token -> rolled source pixel
    }
    const int p_   = R & 63;
    const int win_ = (R >> 6) & 1023;
    const int b_   = R >> 16;
    const int hsrc = (((win_ >> 5) << 3) + (p_ >> 3) + SHIFT) & 255;
    const int wsrc = ((win_ & 31) << 3) + (p_ & 7);
    const float* aBase = emb + ((((size_t)b_ * HH + hsrc) * WW + wsrc) * CC);

    // B-tile loader mapping
    const int brow = tid >> 5;          // 0..7
    const int bcol = (tid & 31) * 4;    // 0..124

    float acc[8][8];
#pragma unroll
    for (int i = 0; i < 8; i++)
#pragma unroll
        for (int j = 0; j < 8; j++) acc[i][j] = 0.f;

    const int ty = tid >> 4, tx = tid & 15;

    for (int k0 = 0; k0 < CC; k0 += 8) {
        float4 av = *reinterpret_cast<const float4*>(aBase + k0 + apart);
        float4 bv = *reinterpret_cast<const float4*>(
            Wq + (size_t)(k0 + brow) * 768 + colBlock * 128 + bcol);
        As[apart + 0][arow] = av.x;
        As[apart + 1][arow] = av.y;
        As[apart + 2][arow] = av.z;
        As[apart + 3][arow] = av.w;
        *reinterpret_cast<float4*>(&Bs[brow][bcol]) = bv;
        __syncthreads();
#pragma unroll
        for (int k = 0; k < 8; ++k) {
            float af[8], bf[8];
            *reinterpret_cast<float4*>(&af[0]) = *reinterpret_cast<const float4*>(&As[k][ty * 4]);
            *reinterpret_cast<float4*>(&af[4]) = *reinterpret_cast<const float4*>(&As[k][64 + ty * 4]);
            *reinterpret_cast<float4*>(&bf[0]) = *reinterpret_cast<const float4*>(&Bs[k][tx * 4]);
            *reinterpret_cast<float4*>(&bf[4]) = *reinterpret_cast<const float4*>(&Bs[k][64 + tx * 4]);
#pragma unroll
            for (int i = 0; i < 8; i++)
#pragma unroll
                for (int j = 0; j < 8; j++)
                    acc[i][j] += af[i] * bf[j];
        }
        __syncthreads();
    }

    // epilogue: add bias, scatter to q/k/v layout
#pragma unroll
    for (int ih = 0; ih < 2; ih++) {
#pragma unroll
        for (int i = 0; i < 4; i++) {
            int r  = rowBlock * 128 + ih * 64 + ty * 4 + i;
            int pr = r & 63;
            int wr = (r >> 6) & 1023;
            int br = r >> 16;
#pragma unroll
            for (int jh = 0; jh < 2; jh++) {
#pragma unroll
                for (int j = 0; j < 4; j++) {
                    int n = colBlock * 128 + jh * 64 + tx * 4 + j;   // 0..767
                    float v = acc[ih * 4 + i][jh * 4 + j] + bq[n];
                    int qkv  = n >> 8;
                    int head = (n >> 5) & 7;
                    int d    = n & 31;
                    size_t idx = (((((size_t)s * 3 + qkv) * BB + br) * NWIN + wr) * NH + head)
                                     * ((size_t)PP * HD)
                                 + (size_t)pr * HD + d;
                    g_qkv[idx] = v;
                }
            }
        }
    }
}

// ---------------------------------------------------------------------------
// Kernel 2: windowed cross-attention.
// block = (b*win, head, stream). q from stream s, k/v from stream 1-s.
// ---------------------------------------------------------------------------
__global__ __launch_bounds__(128)
void attn_kernel()
{
    const int s    = blockIdx.z;
    const int head = blockIdx.y;
    const int bw   = blockIdx.x;           // 0..2047
    const int b    = bw >> 10;
    const int win  = bw & 1023;
    const int os   = 1 - s;

    __shared__ float qs[64][36];
    __shared__ float ks[64][36];
    __shared__ float vs[64][36];
    __shared__ float sim[64][65];

    const int tid = threadIdx.x;           // 128 threads

    const size_t tile = (size_t)PP * HD;   // 2048
    const size_t qbase = (((((size_t)s  * 3 + 0) * BB + b) * NWIN + win) * NH + head) * tile;
    const size_t kbase = (((((size_t)os * 3 + 1) * BB + b) * NWIN + win) * NH + head) * tile;
    const size_t vbase = (((((size_t)os * 3 + 2) * BB + b) * NWIN + win) * NH + head) * tile;

    // load q/k/v tiles (2048 floats each)
#pragma unroll
    for (int it = 0; it < 4; ++it) {
        int e = tid * 4 + it * 512;        // float offset, multiple of 4
        int p = e >> 5, d = e & 31;
        float4 vq = *reinterpret_cast<const float4*>(&g_qkv[qbase + e]);
        qs[p][d] = vq.x; qs[p][d+1] = vq.y; qs[p][d+2] = vq.z; qs[p][d+3] = vq.w;
        float4 vk = *reinterpret_cast<const float4*>(&g_qkv[kbase + e]);
        ks[p][d] = vk.x; ks[p][d+1] = vk.y; ks[p][d+2] = vk.z; ks[p][d+3] = vk.w;
        float4 vv = *reinterpret_cast<const float4*>(&g_qkv[vbase + e]);
        vs[p][d] = vv.x; vs[p][d+1] = vv.y; vs[p][d+2] = vv.z; vs[p][d+3] = vv.w;
    }
    // load bias into sim (coalesced)
    const size_t bb = ((size_t)s * NH + head) * 4096;
#pragma unroll
    for (int e = 0; e < 32; ++e) {
        int idx = tid + e * 128;
        sim[idx >> 6][idx & 63] = g_bias[bb + idx];
    }
    __syncthreads();

    // sim = q.k^T * scale + bias, masked
    const int p  = tid >> 1;
    const int qb = (tid & 1) * 32;
    float qreg[32];
#pragma unroll
    for (int d = 0; d < 32; d += 4) {
        float4 v = *reinterpret_cast<const float4*>(&qs[p][d]);
        qreg[d] = v.x; qreg[d+1] = v.y; qreg[d+2] = v.z; qreg[d+3] = v.w;
    }
    const int  ip = p >> 3, jp = p & 7;
    const bool mh = ((win >> 5) == 31);
    const bool mw = ((win & 31) == 31);
    const float scale = 0.17677669529663687f;   // 1/sqrt(32)

#pragma unroll 4
    for (int qi = 0; qi < 32; ++qi) {
        int qq = qb + qi;
        float acc = 0.f;
#pragma unroll
        for (int d = 0; d < 32; d += 4) {
            float4 kv = *reinterpret_cast<const float4*>(&ks[qq][d]);
            acc += qreg[d] * kv.x + qreg[d+1] * kv.y + qreg[d+2] * kv.z + qreg[d+3] * kv.w;
        }
        float bias = sim[p][qq];
        float val  = acc * scale + bias;
        int iq = qq >> 3, jq = qq & 7;
        bool masked = (mh && ((ip < 4) != (iq < 4))) || (mw && ((jp < 4) != (jq < 4)));
        sim[p][qq] = masked ? -1e30f : val;
    }
    __syncthreads();

    // softmax: one thread per row
    if (tid < 64) {
        float m = -1e30f;
#pragma unroll 8
        for (int q = 0; q < 64; ++q) m = fmaxf(m, sim[tid][q]);
        float sum = 0.f;
#pragma unroll 8
        for (int q = 0; q < 64; ++q) {
            float e = __expf(sim[tid][q] - m);
            sim[tid][q] = e;
            sum += e;
        }
        float inv = 1.f / sum;
#pragma unroll 8
        for (int q = 0; q < 64; ++q) sim[tid][q] *= inv;
    }
    __syncthreads();

    // o = pr @ v : thread handles (row p, 16 d-values)
    const int db = (tid & 1) * 16;
    float o[16];
#pragma unroll
    for (int j = 0; j < 16; j++) o[j] = 0.f;
#pragma unroll 4
    for (int qc = 0; qc < 64; ++qc) {
        float pr = sim[p][qc];
#pragma unroll
        for (int j = 0; j < 16; j += 4) {
            float4 vv = *reinterpret_cast<const float4*>(&vs[qc][db + j]);
            o[j]   += pr * vv.x;
            o[j+1] += pr * vv.y;
            o[j+2] += pr * vv.z;
            o[j+3] += pr * vv.w;
        }
    }
    size_t ob = (size_t)s * ((size_t)BB * NWIN * PP * CC)
              + ((((size_t)b * NWIN + win) * PP + p) * CC)
              + (size_t)head * HD + db;
#pragma unroll
    for (int j = 0; j < 16; j += 4) {
        float4 vv = make_float4(o[j], o[j+1], o[j+2], o[j+3]);
        *reinterpret_cast<float4*>(&g_attn[ob + j]) = vv;
    }
}

// ---------------------------------------------------------------------------
// Kernel 3: output projection GEMM + fused unwindow + roll scatter.
// A: g_attn (M=131072, K=256)  B: Wo (256 x 256)
// ---------------------------------------------------------------------------
__global__ __launch_bounds__(256)
void proj_gemm(const float* __restrict__ Wo1, const float* __restrict__ bo1,
               const float* __restrict__ Wo2, const float* __restrict__ bo2,
               float* __restrict__ out)
{
    const int s = blockIdx.z;
    const float* __restrict__ Wo = s ? Wo2 : Wo1;
    const float* __restrict__ bo = s ? bo2 : bo1;
    float* __restrict__ dst = out + (size_t)s * ((size_t)BB * HH * WW * OUTC);

    __shared__ float As[8][128];
    __shared__ float Bs[8][128];

    const int tid      = threadIdx.x;
    const int rowBlock = blockIdx.y;   // 0..1023
    const int colBlock = blockIdx.x;   // 0..1

    const int arow  = tid >> 1;
    const int apart = (tid & 1) * 4;
    const int R     = rowBlock * 128 + arow;
    const float* aBase = g_attn + (size_t)s * ((size_t)BB * NWIN * PP * CC) + (size_t)R * CC;

    const int brow = tid >> 5;
    const int bcol = (tid & 31) * 4;

    float acc[8][8];
#pragma unroll
    for (int i = 0; i < 8; i++)
#pragma unroll
        for (int j = 0; j < 8; j++) acc[i][j] = 0.f;

    const int ty = tid >> 4, tx = tid & 15;

    for (int k0 = 0; k0 < CC; k0 += 8) {
        float4 av = *reinterpret_cast<const float4*>(aBase + k0 + apart);
        float4 bv = *reinterpret_cast<const float4*>(
            Wo + (size_t)(k0 + brow) * OUTC + colBlock * 128 + bcol);
        As[apart + 0][arow] = av.x;
        As[apart + 1][arow] = av.y;
        As[apart + 2][arow] = av.z;
        As[apart + 3][arow] = av.w;
        *reinterpret_cast<float4*>(&Bs[brow][bcol]) = bv;
        __syncthreads();
#pragma unroll
        for (int k = 0; k < 8; ++k) {
            float af[8], bf[8];
            *reinterpret_cast<float4*>(&af[0]) = *reinterpret_cast<const float4*>(&As[k][ty * 4]);
            *reinterpret_cast<float4*>(&af[4]) = *reinterpret_cast<const float4*>(&As[k][64 + ty * 4]);
            *reinterpret_cast<float4*>(&bf[0]) = *reinterpret_cast<const float4*>(&Bs[k][tx * 4]);
            *reinterpret_cast<float4*>(&bf[4]) = *reinterpret_cast<const float4*>(&Bs[k][64 + tx * 4]);
#pragma unroll
            for (int i = 0; i < 8; i++)
#pragma unroll
                for (int j = 0; j < 8; j++)
                    acc[i][j] += af[i] * bf[j];
        }
        __syncthreads();
    }

    // epilogue: add bias, unwindow + roll scatter
#pragma unroll
    for (int ih = 0; ih < 2; ih++) {
#pragma unroll
        for (int i = 0; i < 4; i++) {
            int r  = rowBlock * 128 + ih * 64 + ty * 4 + i;
            int pr = r & 63;
            int wr = (r >> 6) & 1023;
            int br = r >> 16;
            int hout = (((wr >> 5) << 3) + (pr >> 3) + SHIFT) & 255;
            int wout = ((wr & 31) << 3) + (pr & 7);
            size_t rowbase = (((size_t)br * HH + hout) * WW + wout) * OUTC;
#pragma unroll
            for (int jh = 0; jh < 2; jh++) {
                int n0 = colBlock * 128 + jh * 64 + tx * 4;
                float4 vv;
                vv.x = acc[ih * 4 + i][jh * 4 + 0] + bo[n0 + 0];
                vv.y = acc[ih * 4 + i][jh * 4 + 1] + bo[n0 + 1];
                vv.z = acc[ih * 4 + i][jh * 4 + 2] + bo[n0 + 2];
                vv.w = acc[ih * 4 + i][jh * 4 + 3] + bo[n0 + 3];
                *reinterpret_cast<float4*>(&dst[rowbase + n0]) = vv;
            }
        }
    }
}

// ---------------------------------------------------------------------------
// Launch
// ---------------------------------------------------------------------------
extern "C" void kernel_launch(void* const* d_in, const int* in_sizes, int n_in,
                              void* d_out, int out_size)
{
    const float* emb1  = (const float*)d_in[0];
    const float* emb2  = (const float*)d_in[1];
    const float* Wqkv1 = (const float*)d_in[2];
    const float* bqkv1 = (const float*)d_in[3];
    const float* Wqkv2 = (const float*)d_in[4];
    const float* bqkv2 = (const float*)d_in[5];
    const float* rel1  = (const float*)d_in[6];
    const float* rel2  = (const float*)d_in[7];
    const float* Wo1   = (const float*)d_in[8];
    const float* bo1   = (const float*)d_in[9];
    const float* Wo2   = (const float*)d_in[10];
    const float* bo2   = (const float*)d_in[11];
    float* out = (float*)d_out;

    (void)in_sizes; (void)n_in; (void)out_size;

    bias_kernel<<<256, 256>>>(rel1, rel2);

    dim3 gq(6, 1024, 2);      // N=768/128, M=131072/128, 2 streams
    qkv_gemm<<<gq, 256>>>(emb1, emb2, Wqkv1, bqkv1, Wqkv2, bqkv2);

    dim3 ga(2048, 8, 2);      // (b*win), head, stream
    attn_kernel<<<ga, 128>>>();

    dim3 gp(2, 1024, 2);      // N=256/128, M=131072/128, 2 streams
    proj_gemm<<<gp, 256>>>(Wo1, bo1, Wo2, bo2, out);
}

// round 6
// speedup vs baseline: 1.0006x; 1.0006x over previous
#include <cuda_runtime.h>
#include <cstdint>

// Problem constants
#define BB 2
#define HH 256
#define WW 256
#define CC 256
#define WS 8
#define SHIFT 4
#define NH 8
#define HD 32
#define OUTC 256
#define NWIN 1024      // (H/WS)*(W/WS)
#define PP 64          // WS*WS
#define MROWS 131072   // B*NWIN*PP per stream

// Scratch (device globals; no runtime allocation allowed)
// qkv layout: [stream][qkv][b][win][head][p][d]
__device__ float g_qkv[2u*3u*BB*NWIN*NH*PP*HD];        // 201,326,592 floats
// attn out layout: [stream][b][win][p][C]  (C = head*32+d)
__device__ float g_attn[2u*BB*NWIN*PP*CC];             // 67,108,864 floats
// bias table: [stream][head][p][q]
__device__ float g_bias[2*NH*PP*PP];                   // 65,536 floats

// ---------------------------------------------------------------------------
// Kernel 0: bias table from rel (NH,15,15)
// ---------------------------------------------------------------------------
__global__ void bias_kernel(const float* __restrict__ rel1,
                            const float* __restrict__ rel2)
{
    int idx = blockIdx.x * blockDim.x + threadIdx.x;   // 0 .. 65535
    int s    = idx >> 15;
    int head = (idx >> 12) & 7;
    int p    = (idx >> 6) & 63;
    int q    = idx & 63;
    const float* rel = s ? rel2 : rel1;
    int a = (p >> 3) - (q >> 3) + 7;
    int b = (p & 7) - (q & 7) + 7;
    g_bias[idx] = rel[head * 225 + a * 15 + b];
}

// ---------------------------------------------------------------------------
// Kernel 1: QKV GEMM with fused roll + window gather.
// A: gathered emb rows (M=131072, K=256)   B: Wqkv (256 x 768)
// 128x128x8 tiling, 256 threads, 8x8 register tiles.
// ---------------------------------------------------------------------------
__global__ __launch_bounds__(256)
void qkv_gemm(const float* __restrict__ emb1, const float* __restrict__ emb2,
              const float* __restrict__ Wqkv1, const float* __restrict__ bqkv1,
              const float* __restrict__ Wqkv2, const float* __restrict__ bqkv2)
{
    const int s = blockIdx.z;
    const float* __restrict__ emb = s ? emb2 : emb1;
    const float* __restrict__ Wq  = s ? Wqkv2 : Wqkv1;
    const float* __restrict__ bq  = s ? bqkv2 : bqkv1;

    __shared__ float As[8][128];   // transposed A tile
    __shared__ float Bs[8][128];

    const int tid      = threadIdx.x;
    const int rowBlock = blockIdx.y;   // 0..1023
    const int colBlock = blockIdx.x;   // 0..5

    // A-tile loader mapping: one float4 per thread per k-iter
    const int arow  = tid >> 1;          // 0..127
    const int apart = (tid & 1) * 4;     // 0 or 4
    const int R     = rowBlock * 128 + arow;
    {
        // decode token -> rolled source pixel
    }
    const int p_   = R & 63;
    const int win_ = (R >> 6) & 1023;
    const int b_   = R >> 16;
    const int hsrc = (((win_ >> 5) << 3) + (p_ >> 3) + SHIFT) & 255;
    const int wsrc = ((win_ & 31) << 3) + (p_ & 7);
    const float* aBase = emb + ((((size_t)b_ * HH + hsrc) * WW + wsrc) * CC);

    // B-tile loader mapping
    const int brow = tid >> 5;          // 0..7
    const int bcol = (tid & 31) * 4;    // 0..124

    float acc[8][8];
#pragma unroll
    for (int i = 0; i < 8; i++)
#pragma unroll
        for (int j = 0; j < 8; j++) acc[i][j] = 0.f;

    const int ty = tid >> 4, tx = tid & 15;

    for (int k0 = 0; k0 < CC; k0 += 8) {
        float4 av = *reinterpret_cast<const float4*>(aBase + k0 + apart);
        float4 bv = *reinterpret_cast<const float4*>(
            Wq + (size_t)(k0 + brow) * 768 + colBlock * 128 + bcol);
        As[apart + 0][arow] = av.x;
        As[apart + 1][arow] = av.y;
        As[apart + 2][arow] = av.z;
        As[apart + 3][arow] = av.w;
        *reinterpret_cast<float4*>(&Bs[brow][bcol]) = bv;
        __syncthreads();
#pragma unroll
        for (int k = 0; k < 8; ++k) {
            float af[8], bf[8];
            *reinterpret_cast<float4*>(&af[0]) = *reinterpret_cast<const float4*>(&As[k][ty * 4]);
            *reinterpret_cast<float4*>(&af[4]) = *reinterpret_cast<const float4*>(&As[k][64 + ty * 4]);
            *reinterpret_cast<float4*>(&bf[0]) = *reinterpret_cast<const float4*>(&Bs[k][tx * 4]);
            *reinterpret_cast<float4*>(&bf[4]) = *reinterpret_cast<const float4*>(&Bs[k][64 + tx * 4]);
#pragma unroll
            for (int i = 0; i < 8; i++)
#pragma unroll
                for (int j = 0; j < 8; j++)
                    acc[i][j] += af[i] * bf[j];
        }
        __syncthreads();
    }

    // epilogue: add bias, scatter to q/k/v layout
#pragma unroll
    for (int ih = 0; ih < 2; ih++) {
#pragma unroll
        for (int i = 0; i < 4; i++) {
            int r  = rowBlock * 128 + ih * 64 + ty * 4 + i;
            int pr = r & 63;
            int wr = (r >> 6) & 1023;
            int br = r >> 16;
#pragma unroll
            for (int jh = 0; jh < 2; jh++) {
#pragma unroll
                for (int j = 0; j < 4; j++) {
                    int n = colBlock * 128 + jh * 64 + tx * 4 + j;   // 0..767
                    float v = acc[ih * 4 + i][jh * 4 + j] + bq[n];
                    int qkv  = n >> 8;
                    int head = (n >> 5) & 7;
                    int d    = n & 31;
                    size_t idx = (((((size_t)s * 3 + qkv) * BB + br) * NWIN + wr) * NH + head)
                                     * ((size_t)PP * HD)
                                 + (size_t)pr * HD + d;
                    g_qkv[idx] = v;
                }
            }
        }
    }
}

// ---------------------------------------------------------------------------
// Kernel 2: windowed cross-attention.
// block = (b*win, head, stream). q from stream s, k/v from stream 1-s.
// ---------------------------------------------------------------------------
__global__ __launch_bounds__(128)
void attn_kernel()
{
    const int s    = blockIdx.z;
    const int head = blockIdx.y;
    const int bw   = blockIdx.x;           // 0..2047
    const int b    = bw >> 10;
    const int win  = bw & 1023;
    const int os   = 1 - s;

    __shared__ float qs[64][36];
    __shared__ float ks[64][36];
    __shared__ float vs[64][36];
    __shared__ float sim[64][65];

    const int tid = threadIdx.x;           // 128 threads

    const size_t tile = (size_t)PP * HD;   // 2048
    const size_t qbase = (((((size_t)s  * 3 + 0) * BB + b) * NWIN + win) * NH + head) * tile;
    const size_t kbase = (((((size_t)os * 3 + 1) * BB + b) * NWIN + win) * NH + head) * tile;
    const size_t vbase = (((((size_t)os * 3 + 2) * BB + b) * NWIN + win) * NH + head) * tile;

    // load q/k/v tiles (2048 floats each)
#pragma unroll
    for (int it = 0; it < 4; ++it) {
        int e = tid * 4 + it * 512;        // float offset, multiple of 4
        int p = e >> 5, d = e & 31;
        float4 vq = *reinterpret_cast<const float4*>(&g_qkv[qbase + e]);
        qs[p][d] = vq.x; qs[p][d+1] = vq.y; qs[p][d+2] = vq.z; qs[p][d+3] = vq.w;
        float4 vk = *reinterpret_cast<const float4*>(&g_qkv[kbase + e]);
        ks[p][d] = vk.x; ks[p][d+1] = vk.y; ks[p][d+2] = vk.z; ks[p][d+3] = vk.w;
        float4 vv = *reinterpret_cast<const float4*>(&g_qkv[vbase + e]);
        vs[p][d] = vv.x; vs[p][d+1] = vv.y; vs[p][d+2] = vv.z; vs[p][d+3] = vv.w;
    }
    // load bias into sim (coalesced)
    const size_t bb = ((size_t)s * NH + head) * 4096;
#pragma unroll
    for (int e = 0; e < 32; ++e) {
        int idx = tid + e * 128;
        sim[idx >> 6][idx & 63] = g_bias[bb + idx];
    }
    __syncthreads();

    // sim = q.k^T * scale + bias, masked
    const int p  = tid >> 1;
    const int qb = (tid & 1) * 32;
    float qreg[32];
#pragma unroll
    for (int d = 0; d < 32; d += 4) {
        float4 v = *reinterpret_cast<const float4*>(&qs[p][d]);
        qreg[d] = v.x; qreg[d+1] = v.y; qreg[d+2] = v.z; qreg[d+3] = v.w;
    }
    const int  ip = p >> 3, jp = p & 7;
    const bool mh = ((win >> 5) == 31);
    const bool mw = ((win & 31) == 31);
    const float scale = 0.17677669529663687f;   // 1/sqrt(32)

#pragma unroll 4
    for (int qi = 0; qi < 32; ++qi) {
        int qq = qb + qi;
        float acc = 0.f;
#pragma unroll
        for (int d = 0; d < 32; d += 4) {
            float4 kv = *reinterpret_cast<const float4*>(&ks[qq][d]);
            acc += qreg[d] * kv.x + qreg[d+1] * kv.y + qreg[d+2] * kv.z + qreg[d+3] * kv.w;
        }
        float bias = sim[p][qq];
        float val  = acc * scale + bias;
        int iq = qq >> 3, jq = qq & 7;
        bool masked = (mh && ((ip < 4) != (iq < 4))) || (mw && ((jp < 4) != (jq < 4)));
        sim[p][qq] = masked ? -1e30f : val;
    }
    __syncthreads();

    // softmax: one thread per row
    if (tid < 64) {
        float m = -1e30f;
#pragma unroll 8
        for (int q = 0; q < 64; ++q) m = fmaxf(m, sim[tid][q]);
        float sum = 0.f;
#pragma unroll 8
        for (int q = 0; q < 64; ++q) {
            float e = __expf(sim[tid][q] - m);
            sim[tid][q] = e;
            sum += e;
        }
        float inv = 1.f / sum;
#pragma unroll 8
        for (int q = 0; q < 64; ++q) sim[tid][q] *= inv;
    }
    __syncthreads();

    // o = pr @ v : thread handles (row p, 16 d-values)
    const int db = (tid & 1) * 16;
    float o[16];
#pragma unroll
    for (int j = 0; j < 16; j++) o[j] = 0.f;
#pragma unroll 4
    for (int qc = 0; qc < 64; ++qc) {
        float pr = sim[p][qc];
#pragma unroll
        for (int j = 0; j < 16; j += 4) {
            float4 vv = *reinterpret_cast<const float4*>(&vs[qc][db + j]);
            o[j]   += pr * vv.x;
            o[j+1] += pr * vv.y;
            o[j+2] += pr * vv.z;
            o[j+3] += pr * vv.w;
        }
    }
    size_t ob = (size_t)s * ((size_t)BB * NWIN * PP * CC)
              + ((((size_t)b * NWIN + win) * PP + p) * CC)
              + (size_t)head * HD + db;
#pragma unroll
    for (int j = 0; j < 16; j += 4) {
        float4 vv = make_float4(o[j], o[j+1], o[j+2], o[j+3]);
        *reinterpret_cast<float4*>(&g_attn[ob + j]) = vv;
    }
}

// ---------------------------------------------------------------------------
// Kernel 3: output projection GEMM + fused unwindow + roll scatter.
// A: g_attn (M=131072, K=256)  B: Wo (256 x 256)
// ---------------------------------------------------------------------------
__global__ __launch_bounds__(256)
void proj_gemm(const float* __restrict__ Wo1, const float* __restrict__ bo1,
               const float* __restrict__ Wo2, const float* __restrict__ bo2,
               float* __restrict__ out)
{
    const int s = blockIdx.z;
    const float* __restrict__ Wo = s ? Wo2 : Wo1;
    const float* __restrict__ bo = s ? bo2 : bo1;
    float* __restrict__ dst = out + (size_t)s * ((size_t)BB * HH * WW * OUTC);

    __shared__ float As[8][128];
    __shared__ float Bs[8][128];

    const int tid      = threadIdx.x;
    const int rowBlock = blockIdx.y;   // 0..1023
    const int colBlock = blockIdx.x;   // 0..1

    const int arow  = tid >> 1;
    const int apart = (tid & 1) * 4;
    const int R     = rowBlock * 128 + arow;
    const float* aBase = g_attn + (size_t)s * ((size_t)BB * NWIN * PP * CC) + (size_t)R * CC;

    const int brow = tid >> 5;
    const int bcol = (tid & 31) * 4;

    float acc[8][8];
#pragma unroll
    for (int i = 0; i < 8; i++)
#pragma unroll
        for (int j = 0; j < 8; j++) acc[i][j] = 0.f;

    const int ty = tid >> 4, tx = tid & 15;

    for (int k0 = 0; k0 < CC; k0 += 8) {
        float4 av = *reinterpret_cast<const float4*>(aBase + k0 + apart);
        float4 bv = *reinterpret_cast<const float4*>(
            Wo + (size_t)(k0 + brow) * OUTC + colBlock * 128 + bcol);
        As[apart + 0][arow] = av.x;
        As[apart + 1][arow] = av.y;
        As[apart + 2][arow] = av.z;
        As[apart + 3][arow] = av.w;
        *reinterpret_cast<float4*>(&Bs[brow][bcol]) = bv;
        __syncthreads();
#pragma unroll
        for (int k = 0; k < 8; ++k) {
            float af[8], bf[8];
            *reinterpret_cast<float4*>(&af[0]) = *reinterpret_cast<const float4*>(&As[k][ty * 4]);
            *reinterpret_cast<float4*>(&af[4]) = *reinterpret_cast<const float4*>(&As[k][64 + ty * 4]);
            *reinterpret_cast<float4*>(&bf[0]) = *reinterpret_cast<const float4*>(&Bs[k][tx * 4]);
            *reinterpret_cast<float4*>(&bf[4]) = *reinterpret_cast<const float4*>(&Bs[k][64 + tx * 4]);
#pragma unroll
            for (int i = 0; i < 8; i++)
#pragma unroll
                for (int j = 0; j < 8; j++)
                    acc[i][j] += af[i] * bf[j];
        }
        __syncthreads();
    }

    // epilogue: add bias, unwindow + roll scatter
#pragma unroll
    for (int ih = 0; ih < 2; ih++) {
#pragma unroll
        for (int i = 0; i < 4; i++) {
            int r  = rowBlock * 128 + ih * 64 + ty * 4 + i;
            int pr = r & 63;
            int wr = (r >> 6) & 1023;
            int br = r >> 16;
            int hout = (((wr >> 5) << 3) + (pr >> 3) + SHIFT) & 255;
            int wout = ((wr & 31) << 3) + (pr & 7);
            size_t rowbase = (((size_t)br * HH + hout) * WW + wout) * OUTC;
#pragma unroll
            for (int jh = 0; jh < 2; jh++) {
                int n0 = colBlock * 128 + jh * 64 + tx * 4;
                float4 vv;
                vv.x = acc[ih * 4 + i][jh * 4 + 0] + bo[n0 + 0];
                vv.y = acc[ih * 4 + i][jh * 4 + 1] + bo[n0 + 1];
                vv.z = acc[ih * 4 + i][jh * 4 + 2] + bo[n0 + 2];
                vv.w = acc[ih * 4 + i][jh * 4 + 3] + bo[n0 + 3];
                *reinterpret_cast<float4*>(&dst[rowbase + n0]) = vv;
            }
        }
    }
}

// ---------------------------------------------------------------------------
// Launch
// ---------------------------------------------------------------------------
extern "C" void kernel_launch(void* const* d_in, const int* in_sizes, int n_in,
                              void* d_out, int out_size)
{
    const float* emb1  = (const float*)d_in[0];
    const float* emb2  = (const float*)d_in[1];
    const float* Wqkv1 = (const float*)d_in[2];
    const float* bqkv1 = (const float*)d_in[3];
    const float* Wqkv2 = (const float*)d_in[4];
    const float* bqkv2 = (const float*)d_in[5];
    const float* rel1  = (const float*)d_in[6];
    const float* rel2  = (const float*)d_in[7];
    const float* Wo1   = (const float*)d_in[8];
    const float* bo1   = (const float*)d_in[9];
    const float* Wo2   = (const float*)d_in[10];
    const float* bo2   = (const float*)d_in[11];
    float* out = (float*)d_out;

    (void)in_sizes; (void)n_in; (void)out_size;

    bias_kernel<<<256, 256>>>(rel1, rel2);

    dim3 gq(6, 1024, 2);      // N=768/128, M=131072/128, 2 streams
    qkv_gemm<<<gq, 256>>>(emb1, emb2, Wqkv1, bqkv1, Wqkv2, bqkv2);

    dim3 ga(2048, 8, 2);      // (b*win), head, stream
    attn_kernel<<<ga, 128>>>();

    dim3 gp(2, 1024, 2);      // N=256/128, M=131072/128, 2 streams
    proj_gemm<<<gp, 256>>>(Wo1, bo1, Wo2, bo2, out);
}

// round 8
// speedup vs baseline: 1.5533x; 1.5524x over previous
#include <cuda_runtime.h>
#include <cstdint>

// Problem constants
#define BB 2
#define HH 256
#define WW 256
#define CC 256
#define WS 8
#define SHIFT 4
#define NH 8
#define HD 32
#define OUTC 256
#define NWIN 1024
#define PP 64
#define MROWS 131072

// Scratch (device globals)
__device__ float g_qkv[2u*3u*BB*NWIN*NH*PP*HD];   // [s][qkv][b][win][head][p][d]
__device__ float g_attn[2u*BB*NWIN*PP*CC];        // [s][b][win][p][C]
__device__ float g_bias[2*NH*PP*PP];

__device__ __forceinline__ float to_tf32(float x) {
    float r;
    asm("cvt.rna.tf32.f32 %0, %1;" : "=f"(r) : "f"(x));
    return r;
}

__device__ __forceinline__ void mma_tf32_16n8k8(float c[4],
                                                float a0, float a1, float a2, float a3,
                                                float b0, float b1) {
    asm volatile(
        "mma.sync.aligned.m16n8k8.row.col.f32.tf32.tf32.f32 "
        "{%0,%1,%2,%3}, {%4,%5,%6,%7}, {%8,%9}, {%0,%1,%2,%3};"
        : "+f"(c[0]), "+f"(c[1]), "+f"(c[2]), "+f"(c[3])
        : "f"(a0), "f"(a1), "f"(a2), "f"(a3), "f"(b0), "f"(b1));
}

#define APITCH 36
#define BPITCH 132

// ---------------------------------------------------------------------------
// Kernel 0: bias table
// ---------------------------------------------------------------------------
__global__ void bias_kernel(const float* __restrict__ rel1,
                            const float* __restrict__ rel2)
{
    int idx = blockIdx.x * blockDim.x + threadIdx.x;
    int s = idx >> 15, head = (idx >> 12) & 7, p = (idx >> 6) & 63, q = idx & 63;
    const float* rel = s ? rel2 : rel1;
    int a = (p >> 3) - (q >> 3) + 7;
    int b = (p & 7) - (q & 7) + 7;
    g_bias[idx] = rel[head * 225 + a * 15 + b];
}

// ---------------------------------------------------------------------------
// Kernel 1: QKV GEMM (tf32 mma.sync).  M=131072, N=768, K=256 per stream.
// 128x128 tile, 8 warps, warp tile 32x64, K chunks of 32.
// ---------------------------------------------------------------------------
__global__ __launch_bounds__(256)
void qkv_mma(const float* __restrict__ emb1, const float* __restrict__ emb2,
             const float* __restrict__ Wqkv1, const float* __restrict__ bqkv1,
             const float* __restrict__ Wqkv2, const float* __restrict__ bqkv2)
{
    __shared__ float As[128 * APITCH];
    __shared__ float Bs[32 * BPITCH];

    const int s = blockIdx.z;
    const float* __restrict__ emb = s ? emb2 : emb1;
    const float* __restrict__ Wq  = s ? Wqkv2 : Wqkv1;
    const float* __restrict__ bq  = s ? bqkv2 : bqkv1;
    const int colBlock = blockIdx.x;     // 0..5
    const int rowBlock = blockIdx.y;     // 0..1023
    const int tid  = threadIdx.x;
    const int wid  = tid >> 5;
    const int lane = tid & 31;
    const int g    = lane >> 2;          // 0..7
    const int t4   = lane & 3;           // 0..3

    // A loader: row tid>>1 (0..127), cols (tid&1)*16 .. +15 per chunk
    const int arow = tid >> 1;
    const int acol = (tid & 1) * 16;
    int R = rowBlock * 128 + arow;
    int p_ = R & 63, win_ = (R >> 6) & 1023, b_ = R >> 16;
    int hs = (((win_ >> 5) << 3) + (p_ >> 3) + SHIFT) & 255;
    int wsrc = ((win_ & 31) << 3) + (p_ & 7);
    const float* aRow = emb + ((((size_t)b_ * HH + hs) * WW + wsrc) * CC);

    // B loader: k-row tid>>3 (0..31), cols (tid&7)*16 .. +15
    const int bk = tid >> 3;
    const int bc = (tid & 7) * 16;

    const int wrb = (wid & 3) * 32;
    const int wcb = (wid >> 2) * 64;

    float acc[2][8][4];
#pragma unroll
    for (int mi = 0; mi < 2; mi++)
#pragma unroll
        for (int nj = 0; nj < 8; nj++)
#pragma unroll
            for (int k = 0; k < 4; k++) acc[mi][nj][k] = 0.f;

    float4 aPre[4], bPre[4];
#pragma unroll
    for (int j = 0; j < 4; ++j) {
        aPre[j] = *reinterpret_cast<const float4*>(aRow + acol + j * 4);
        bPre[j] = *reinterpret_cast<const float4*>(
            Wq + (size_t)bk * 768 + colBlock * 128 + bc + j * 4);
    }

    for (int c = 0; c < 8; ++c) {
#pragma unroll
        for (int j = 0; j < 4; ++j) {
            float4 v = aPre[j];
            float* d = &As[arow * APITCH + acol + j * 4];
            d[0] = to_tf32(v.x); d[1] = to_tf32(v.y);
            d[2] = to_tf32(v.z); d[3] = to_tf32(v.w);
            float4 w = bPre[j];
            float* e = &Bs[bk * BPITCH + bc + j * 4];
            e[0] = to_tf32(w.x); e[1] = to_tf32(w.y);
            e[2] = to_tf32(w.z); e[3] = to_tf32(w.w);
        }
        __syncthreads();
        if (c < 7) {
            int k0n = (c + 1) * 32;
#pragma unroll
            for (int j = 0; j < 4; ++j) {
                aPre[j] = *reinterpret_cast<const float4*>(aRow + k0n + acol + j * 4);
                bPre[j] = *reinterpret_cast<const float4*>(
                    Wq + (size_t)(k0n + bk) * 768 + colBlock * 128 + bc + j * 4);
            }
        }
#pragma unroll
        for (int kk = 0; kk < 4; ++kk) {
            int k0 = kk * 8;
            float a[2][4];
#pragma unroll
            for (int mi = 0; mi < 2; mi++) {
                int r0 = wrb + mi * 16 + g;
                a[mi][0] = As[r0 * APITCH + k0 + t4];
                a[mi][1] = As[(r0 + 8) * APITCH + k0 + t4];
                a[mi][2] = As[r0 * APITCH + k0 + t4 + 4];
                a[mi][3] = As[(r0 + 8) * APITCH + k0 + t4 + 4];
            }
#pragma unroll
            for (int nj = 0; nj < 8; nj++) {
                int n = wcb + nj * 8 + g;
                float b0 = Bs[(k0 + t4) * BPITCH + n];
                float b1 = Bs[(k0 + t4 + 4) * BPITCH + n];
#pragma unroll
                for (int mi = 0; mi < 2; mi++)
                    mma_tf32_16n8k8(acc[mi][nj],
                                    a[mi][0], a[mi][1], a[mi][2], a[mi][3],
                                    b0, b1);
            }
        }
        __syncthreads();
    }

    // Epilogue: scatter to q/k/v layout
#pragma unroll
    for (int mi = 0; mi < 2; mi++) {
#pragma unroll
        for (int h = 0; h < 2; h++) {
            int r  = rowBlock * 128 + wrb + mi * 16 + g + 8 * h;
            int pr = r & 63, wr = (r >> 6) & 1023, br = r >> 16;
#pragma unroll
            for (int nj = 0; nj < 8; nj++) {
                int n = colBlock * 128 + wcb + nj * 8 + t4 * 2;
                float2 v;
                v.x = acc[mi][nj][h * 2 + 0] + bq[n];
                v.y = acc[mi][nj][h * 2 + 1] + bq[n + 1];
                int qkvi = n >> 8, head = (n >> 5) & 7, d = n & 31;
                size_t idx = ((((size_t)(s * 3 + qkvi) * BB + br) * NWIN + wr) * NH + head)
                                 * ((size_t)PP * HD)
                             + (size_t)pr * HD + d;
                *reinterpret_cast<float2*>(&g_qkv[idx]) = v;
            }
        }
    }
}

// ---------------------------------------------------------------------------
// Kernel 2: windowed cross-attention (SIMT, unchanged).
// ---------------------------------------------------------------------------
__global__ __launch_bounds__(128)
void attn_kernel()
{
    const int s    = blockIdx.z;
    const int head = blockIdx.y;
    const int bw   = blockIdx.x;
    const int b    = bw >> 10;
    const int win  = bw & 1023;
    const int os   = 1 - s;

    __shared__ float qs[64][36];
    __shared__ float ks[64][36];
    __shared__ float vs[64][36];
    __shared__ float sim[64][65];

    const int tid = threadIdx.x;
    const size_t tile = (size_t)PP * HD;
    const size_t qbase = (((((size_t)s  * 3 + 0) * BB + b) * NWIN + win) * NH + head) * tile;
    const size_t kbase = (((((size_t)os * 3 + 1) * BB + b) * NWIN + win) * NH + head) * tile;
    const size_t vbase = (((((size_t)os * 3 + 2) * BB + b) * NWIN + win) * NH + head) * tile;

#pragma unroll
    for (int it = 0; it < 4; ++it) {
        int e = tid * 4 + it * 512;
        int p = e >> 5, d = e & 31;
        float4 vq = *reinterpret_cast<const float4*>(&g_qkv[qbase + e]);
        qs[p][d] = vq.x; qs[p][d+1] = vq.y; qs[p][d+2] = vq.z; qs[p][d+3] = vq.w;
        float4 vk = *reinterpret_cast<const float4*>(&g_qkv[kbase + e]);
        ks[p][d] = vk.x; ks[p][d+1] = vk.y; ks[p][d+2] = vk.z; ks[p][d+3] = vk.w;
        float4 vv = *reinterpret_cast<const float4*>(&g_qkv[vbase + e]);
        vs[p][d] = vv.x; vs[p][d+1] = vv.y; vs[p][d+2] = vv.z; vs[p][d+3] = vv.w;
    }
    const size_t bb = ((size_t)s * NH + head) * 4096;
#pragma unroll
    for (int e = 0; e < 32; ++e) {
        int idx = tid + e * 128;
        sim[idx >> 6][idx & 63] = g_bias[bb + idx];
    }
    __syncthreads();

    const int p  = tid >> 1;
    const int qb = (tid & 1) * 32;
    float qreg[32];
#pragma unroll
    for (int d = 0; d < 32; d += 4) {
        float4 v = *reinterpret_cast<const float4*>(&qs[p][d]);
        qreg[d] = v.x; qreg[d+1] = v.y; qreg[d+2] = v.z; qreg[d+3] = v.w;
    }
    const int  ip = p >> 3, jp = p & 7;
    const bool mh = ((win >> 5) == 31);
    const bool mw = ((win & 31) == 31);
    const float scale = 0.17677669529663687f;

#pragma unroll 4
    for (int qi = 0; qi < 32; ++qi) {
        int qq = qb + qi;
        float acc = 0.f;
#pragma unroll
        for (int d = 0; d < 32; d += 4) {
            float4 kv = *reinterpret_cast<const float4*>(&ks[qq][d]);
            acc += qreg[d] * kv.x + qreg[d+1] * kv.y + qreg[d+2] * kv.z + qreg[d+3] * kv.w;
        }
        float bias = sim[p][qq];
        float val  = acc * scale + bias;
        int iq = qq >> 3, jq = qq & 7;
        bool masked = (mh && ((ip < 4) != (iq < 4))) || (mw && ((jp < 4) != (jq < 4)));
        sim[p][qq] = masked ? -1e30f : val;
    }
    __syncthreads();

    if (tid < 64) {
        float m = -1e30f;
#pragma unroll 8
        for (int q = 0; q < 64; ++q) m = fmaxf(m, sim[tid][q]);
        float sum = 0.f;
#pragma unroll 8
        for (int q = 0; q < 64; ++q) {
            float e = __expf(sim[tid][q] - m);
            sim[tid][q] = e;
            sum += e;
        }
        float inv = 1.f / sum;
#pragma unroll 8
        for (int q = 0; q < 64; ++q) sim[tid][q] *= inv;
    }
    __syncthreads();

    const int db = (tid & 1) * 16;
    float o[16];
#pragma unroll
    for (int j = 0; j < 16; j++) o[j] = 0.f;
#pragma unroll 4
    for (int qc = 0; qc < 64; ++qc) {
        float pr = sim[p][qc];
#pragma unroll
        for (int j = 0; j < 16; j += 4) {
            float4 vv = *reinterpret_cast<const float4*>(&vs[qc][db + j]);
            o[j]   += pr * vv.x;
            o[j+1] += pr * vv.y;
            o[j+2] += pr * vv.z;
            o[j+3] += pr * vv.w;
        }
    }
    size_t ob = (size_t)s * ((size_t)BB * NWIN * PP * CC)
              + ((((size_t)b * NWIN + win) * PP + p) * CC)
              + (size_t)head * HD + db;
#pragma unroll
    for (int j = 0; j < 16; j += 4) {
        float4 vv = make_float4(o[j], o[j+1], o[j+2], o[j+3]);
        *reinterpret_cast<float4*>(&g_attn[ob + j]) = vv;
    }
}

// ---------------------------------------------------------------------------
// Kernel 3: output projection (tf32 mma.sync) + fused unwindow + roll scatter.
// ---------------------------------------------------------------------------
__global__ __launch_bounds__(256)
void proj_mma(const float* __restrict__ Wo1, const float* __restrict__ bo1,
              const float* __restrict__ Wo2, const float* __restrict__ bo2,
              float* __restrict__ out)
{
    __shared__ float As[128 * APITCH];
    __shared__ float Bs[32 * BPITCH];

    const int s = blockIdx.z;
    const float* __restrict__ Wo = s ? Wo2 : Wo1;
    const float* __restrict__ bo = s ? bo2 : bo1;
    float* __restrict__ dst = out + (size_t)s * ((size_t)BB * HH * WW * OUTC);
    const int colBlock = blockIdx.x;     // 0..1
    const int rowBlock = blockIdx.y;     // 0..1023
    const int tid  = threadIdx.x;
    const int wid  = tid >> 5;
    const int lane = tid & 31;
    const int g    = lane >> 2;
    const int t4   = lane & 3;

    const int arow = tid >> 1;
    const int acol = (tid & 1) * 16;
    const float* aRow = g_attn + (size_t)s * ((size_t)BB * NWIN * PP * CC)
                      + (size_t)(rowBlock * 128 + arow) * CC;

    const int bk = tid >> 3;
    const int bc = (tid & 7) * 16;

    const int wrb = (wid & 3) * 32;
    const int wcb = (wid >> 2) * 64;

    float acc[2][8][4];
#pragma unroll
    for (int mi = 0; mi < 2; mi++)
#pragma unroll
        for (int nj = 0; nj < 8; nj++)
#pragma unroll
            for (int k = 0; k < 4; k++) acc[mi][nj][k] = 0.f;

    float4 aPre[4], bPre[4];
#pragma unroll
    for (int j = 0; j < 4; ++j) {
        aPre[j] = *reinterpret_cast<const float4*>(aRow + acol + j * 4);
        bPre[j] = *reinterpret_cast<const float4*>(
            Wo + (size_t)bk * OUTC + colBlock * 128 + bc + j * 4);
    }

    for (int c = 0; c < 8; ++c) {
#pragma unroll
        for (int j = 0; j < 4; ++j) {
            float4 v = aPre[j];
            float* d = &As[arow * APITCH + acol + j * 4];
            d[0] = to_tf32(v.x); d[1] = to_tf32(v.y);
            d[2] = to_tf32(v.z); d[3] = to_tf32(v.w);
            float4 w = bPre[j];
            float* e = &Bs[bk * BPITCH + bc + j * 4];
            e[0] = to_tf32(w.x); e[1] = to_tf32(w.y);
            e[2] = to_tf32(w.z); e[3] = to_tf32(w.w);
        }
        __syncthreads();
        if (c < 7) {
            int k0n = (c + 1) * 32;
#pragma unroll
            for (int j = 0; j < 4; ++j) {
                aPre[j] = *reinterpret_cast<const float4*>(aRow + k0n + acol + j * 4);
                bPre[j] = *reinterpret_cast<const float4*>(
                    Wo + (size_t)(k0n + bk) * OUTC + colBlock * 128 + bc + j * 4);
            }
        }
#pragma unroll
        for (int kk = 0; kk < 4; ++kk) {
            int k0 = kk * 8;
            float a[2][4];
#pragma unroll
            for (int mi = 0; mi < 2; mi++) {
                int r0 = wrb + mi * 16 + g;
                a[mi][0] = As[r0 * APITCH + k0 + t4];
                a[mi][1] = As[(r0 + 8) * APITCH + k0 + t4];
                a[mi][2] = As[r0 * APITCH + k0 + t4 + 4];
                a[mi][3] = As[(r0 + 8) * APITCH + k0 + t4 + 4];
            }
#pragma unroll
            for (int nj = 0; nj < 8; nj++) {
                int n = wcb + nj * 8 + g;
                float b0 = Bs[(k0 + t4) * BPITCH + n];
                float b1 = Bs[(k0 + t4 + 4) * BPITCH + n];
#pragma unroll
                for (int mi = 0; mi < 2; mi++)
                    mma_tf32_16n8k8(acc[mi][nj],
                                    a[mi][0], a[mi][1], a[mi][2], a[mi][3],
                                    b0, b1);
            }
        }
        __syncthreads();
    }

    // Epilogue: unwindow + roll scatter
#pragma unroll
    for (int mi = 0; mi < 2; mi++) {
#pragma unroll
        for (int h = 0; h < 2; h++) {
            int r  = rowBlock * 128 + wrb + mi * 16 + g + 8 * h;
            int pr = r & 63, wr = (r >> 6) & 1023, br = r >> 16;
            int hout = (((wr >> 5) << 3) + (pr >> 3) + SHIFT) & 255;
            int wout = ((wr & 31) << 3) + (pr & 7);
            size_t rowbase = (((size_t)br * HH + hout) * WW + wout) * OUTC;
#pragma unroll
            for (int nj = 0; nj < 8; nj++) {
                int n = colBlock * 128 + wcb + nj * 8 + t4 * 2;
                float2 v;
                v.x = acc[mi][nj][h * 2 + 0] + bo[n];
                v.y = acc[mi][nj][h * 2 + 1] + bo[n + 1];
                *reinterpret_cast<float2*>(&dst[rowbase + n]) = v;
            }
        }
    }
}

// ---------------------------------------------------------------------------
// Launch
// ---------------------------------------------------------------------------
extern "C" void kernel_launch(void* const* d_in, const int* in_sizes, int n_in,
                              void* d_out, int out_size)
{
    const float* emb1  = (const float*)d_in[0];
    const float* emb2  = (const float*)d_in[1];
    const float* Wqkv1 = (const float*)d_in[2];
    const float* bqkv1 = (const float*)d_in[3];
    const float* Wqkv2 = (const float*)d_in[4];
    const float* bqkv2 = (const float*)d_in[5];
    const float* rel1  = (const float*)d_in[6];
    const float* rel2  = (const float*)d_in[7];
    const float* Wo1   = (const float*)d_in[8];
    const float* bo1   = (const float*)d_in[9];
    const float* Wo2   = (const float*)d_in[10];
    const float* bo2   = (const float*)d_in[11];
    float* out = (float*)d_out;
    (void)in_sizes; (void)n_in; (void)out_size;

    bias_kernel<<<256, 256>>>(rel1, rel2);

    dim3 gq(6, 1024, 2);
    qkv_mma<<<gq, 256>>>(emb1, emb2, Wqkv1, bqkv1, Wqkv2, bqkv2);

    dim3 ga(2048, 8, 2);
    attn_kernel<<<ga, 128>>>();

    dim3 gp(2, 1024, 2);
    proj_mma<<<gp, 256>>>(Wo1, bo1, Wo2, bo2, out);
}

// round 9
// speedup vs baseline: 2.2466x; 1.4463x over previous
#include <cuda_runtime.h>
#include <cstdint>

// Problem constants
#define BB 2
#define HH 256
#define WW 256
#define CC 256
#define WS 8
#define SHIFT 4
#define NH 8
#define HD 32
#define OUTC 256
#define NWIN 1024
#define PP 64
#define MROWS 131072

// Scratch (device globals)
__device__ float g_qkv[2u*3u*BB*NWIN*NH*PP*HD];   // [s][qkv][b][win][head][p][d]
__device__ float g_attn[2u*BB*NWIN*PP*CC];        // [s][b][win][p][C]
__device__ float g_bias[2*NH*PP*PP];
// Packed weights, fragment-ready: per (s,cb): [kc(8)][pr(16)][nl(128)][2]
//   qkv region: 12 * 32768 = 393216 floats, proj region: 4 * 32768 = 131072
__device__ float g_wpack[524288];

__device__ __forceinline__ float to_tf32(float x) {
    float r;
    asm("cvt.rna.tf32.f32 %0, %1;" : "=f"(r) : "f"(x));
    return r;
}

__device__ __forceinline__ void mma_tf32_16n8k8(float c[4],
                                                float a0, float a1, float a2, float a3,
                                                float b0, float b1) {
    asm volatile(
        "mma.sync.aligned.m16n8k8.row.col.f32.tf32.tf32.f32 "
        "{%0,%1,%2,%3}, {%4,%5,%6,%7}, {%8,%9}, {%0,%1,%2,%3};"
        : "+f"(c[0]), "+f"(c[1]), "+f"(c[2]), "+f"(c[3])
        : "f"(a0), "f"(a1), "f"(a2), "f"(a3), "f"(b0), "f"(b1));
}

#define AP2 40     // A smem pitch (floats), pair-interleaved k
#define BROW 264   // B smem row (floats) per pairRow: 128 n * 2 + 8 pad

// ---------------------------------------------------------------------------
// Kernel 0a: bias table
// ---------------------------------------------------------------------------
__global__ void bias_kernel(const float* __restrict__ rel1,
                            const float* __restrict__ rel2)
{
    int idx = blockIdx.x * blockDim.x + threadIdx.x;
    int s = idx >> 15, head = (idx >> 12) & 7, p = (idx >> 6) & 63, q = idx & 63;
    const float* rel = s ? rel2 : rel1;
    int a = (p >> 3) - (q >> 3) + 7;
    int b = (p & 7) - (q & 7) + 7;
    g_bias[idx] = rel[head * 225 + a * 15 + b];
}

// ---------------------------------------------------------------------------
// Kernel 0b: pack weights into fragment-ready layout (tf32-rounded)
//   element (s,cb,kc,pr,nl,h) -> W[k][n], k = kc*32 + (pr>>2)*8 + h*4 + (pr&3),
//   n = cb*128 + nl.
// ---------------------------------------------------------------------------
__global__ void wpack_kernel(const float* __restrict__ Wqkv1,
                             const float* __restrict__ Wqkv2,
                             const float* __restrict__ Wo1,
                             const float* __restrict__ Wo2)
{
    int idx = blockIdx.x * blockDim.x + threadIdx.x;   // 0..524287
    const float* W;
    int N, cb, r;
    if (idx < 393216) {
        int scb = idx >> 15;            // 0..11
        r = idx & 32767;
        int s = scb / 6; cb = scb % 6;
        W = s ? Wqkv2 : Wqkv1; N = 768;
    } else {
        int t = idx - 393216;
        int scb = t >> 15;              // 0..3
        r = t & 32767;
        int s = scb >> 1; cb = scb & 1;
        W = s ? Wo2 : Wo1; N = 256;
    }
    int kc = r >> 12;
    int r2 = r & 4095;
    int pr = r2 >> 8;
    int r3 = r2 & 255;
    int nl = r3 >> 1, h = r3 & 1;
    int k = kc * 32 + (pr >> 2) * 8 + h * 4 + (pr & 3);
    int n = cb * 128 + nl;
    g_wpack[idx] = to_tf32(W[k * N + n]);
}

// ---------------------------------------------------------------------------
// Kernel 1: QKV GEMM (tf32 mma, v2 fragment loads).
// ---------------------------------------------------------------------------
__global__ __launch_bounds__(256)
void qkv_mma(const float* __restrict__ emb1, const float* __restrict__ emb2,
             const float* __restrict__ bqkv1, const float* __restrict__ bqkv2)
{
    __shared__ __align__(16) float As2[128 * AP2];
    __shared__ __align__(16) float Bs2[16 * BROW];

    const int s = blockIdx.z;
    const float* __restrict__ emb = s ? emb2 : emb1;
    const float* __restrict__ bq  = s ? bqkv2 : bqkv1;
    const int colBlock = blockIdx.x;     // 0..5
    const int rowBlock = blockIdx.y;     // 0..1023
    const int tid  = threadIdx.x;
    const int wid  = tid >> 5;
    const int lane = tid & 31;
    const int g    = lane >> 2;
    const int t4   = lane & 3;

    // A loader: row tid>>1 (0..127), k-cols (tid&1)*16 .. +15 per chunk
    const int arow = tid >> 1;
    const int acol = (tid & 1) * 16;
    const int kkbase = acol >> 3;        // 0 or 2
    int R = rowBlock * 128 + arow;
    int p_ = R & 63, win_ = (R >> 6) & 1023, b_ = R >> 16;
    int hs = (((win_ >> 5) << 3) + (p_ >> 3) + SHIFT) & 255;
    int wsrc = ((win_ & 31) << 3) + (p_ & 7);
    const float* aRow = emb + ((((size_t)b_ * HH + hs) * WW + wsrc) * CC);

    const float4* wp4 = reinterpret_cast<const float4*>(g_wpack)
                      + (size_t)(s * 6 + colBlock) * 8192;

    const int wrb = (wid & 3) * 32;
    const int wcb = (wid >> 2) * 64;

    float acc[2][8][4];
#pragma unroll
    for (int mi = 0; mi < 2; mi++)
#pragma unroll
        for (int nj = 0; nj < 8; nj++)
#pragma unroll
            for (int k = 0; k < 4; k++) acc[mi][nj][k] = 0.f;

    float4 aPre[4], bPre[4];
#pragma unroll
    for (int j = 0; j < 4; ++j) {
        aPre[j] = *reinterpret_cast<const float4*>(aRow + acol + j * 4);
        bPre[j] = wp4[tid + j * 256];
    }

    for (int c = 0; c < 8; ++c) {
        // A pair stores: (k, k+4) adjacent
        {
            float* dst0 = &As2[arow * AP2 + kkbase * 8];
            float* dst1 = dst0 + 8;
            float2 v;
            v.x = to_tf32(aPre[0].x); v.y = to_tf32(aPre[1].x);
            *reinterpret_cast<float2*>(dst0 + 0) = v;
            v.x = to_tf32(aPre[0].y); v.y = to_tf32(aPre[1].y);
            *reinterpret_cast<float2*>(dst0 + 2) = v;
            v.x = to_tf32(aPre[0].z); v.y = to_tf32(aPre[1].z);
            *reinterpret_cast<float2*>(dst0 + 4) = v;
            v.x = to_tf32(aPre[0].w); v.y = to_tf32(aPre[1].w);
            *reinterpret_cast<float2*>(dst0 + 6) = v;
            v.x = to_tf32(aPre[2].x); v.y = to_tf32(aPre[3].x);
            *reinterpret_cast<float2*>(dst1 + 0) = v;
            v.x = to_tf32(aPre[2].y); v.y = to_tf32(aPre[3].y);
            *reinterpret_cast<float2*>(dst1 + 2) = v;
            v.x = to_tf32(aPre[2].z); v.y = to_tf32(aPre[3].z);
            *reinterpret_cast<float2*>(dst1 + 4) = v;
            v.x = to_tf32(aPre[2].w); v.y = to_tf32(aPre[3].w);
            *reinterpret_cast<float2*>(dst1 + 6) = v;
        }
        // B copy (already tf32, already fragment-ordered)
#pragma unroll
        for (int i = 0; i < 4; ++i) {
            int v = tid + i * 256;
            *reinterpret_cast<float4*>(&Bs2[(v >> 6) * BROW + (v & 63) * 4]) = bPre[i];
        }
        __syncthreads();
        if (c < 7) {
            int k0n = (c + 1) * 32;
#pragma unroll
            for (int j = 0; j < 4; ++j) {
                aPre[j] = *reinterpret_cast<const float4*>(aRow + k0n + acol + j * 4);
                bPre[j] = wp4[(size_t)(c + 1) * 1024 + tid + j * 256];
            }
        }
#pragma unroll
        for (int kk = 0; kk < 4; ++kk) {
            float a[2][4];
#pragma unroll
            for (int mi = 0; mi < 2; mi++) {
                int r0 = wrb + mi * 16 + g;
                float2 lo = *reinterpret_cast<const float2*>(&As2[r0 * AP2 + kk * 8 + t4 * 2]);
                float2 hi = *reinterpret_cast<const float2*>(&As2[(r0 + 8) * AP2 + kk * 8 + t4 * 2]);
                a[mi][0] = lo.x; a[mi][1] = hi.x; a[mi][2] = lo.y; a[mi][3] = hi.y;
            }
            const float* brow = &Bs2[(kk * 4 + t4) * BROW];
#pragma unroll
            for (int nj = 0; nj < 8; nj++) {
                int n = wcb + nj * 8 + g;
                float2 b = *reinterpret_cast<const float2*>(brow + n * 2);
#pragma unroll
                for (int mi = 0; mi < 2; mi++)
                    mma_tf32_16n8k8(acc[mi][nj],
                                    a[mi][0], a[mi][1], a[mi][2], a[mi][3],
                                    b.x, b.y);
            }
        }
        __syncthreads();
    }

    // Epilogue: scatter to q/k/v layout
#pragma unroll
    for (int mi = 0; mi < 2; mi++) {
#pragma unroll
        for (int h = 0; h < 2; h++) {
            int r  = rowBlock * 128 + wrb + mi * 16 + g + 8 * h;
            int pr = r & 63, wr = (r >> 6) & 1023, br = r >> 16;
#pragma unroll
            for (int nj = 0; nj < 8; nj++) {
                int n = colBlock * 128 + wcb + nj * 8 + t4 * 2;
                float2 v;
                v.x = acc[mi][nj][h * 2 + 0] + bq[n];
                v.y = acc[mi][nj][h * 2 + 1] + bq[n + 1];
                int qkvi = n >> 8, head = (n >> 5) & 7, d = n & 31;
                size_t idx = ((((size_t)(s * 3 + qkvi) * BB + br) * NWIN + wr) * NH + head)
                                 * ((size_t)PP * HD)
                             + (size_t)pr * HD + d;
                *reinterpret_cast<float2*>(&g_qkv[idx]) = v;
            }
        }
    }
}

// ---------------------------------------------------------------------------
// Kernel 2: windowed cross-attention, tensor-core (tf32 mma) version.
// Block = (b*win, head, stream), 128 threads = 4 warps, 16 rows each.
// ---------------------------------------------------------------------------
__global__ __launch_bounds__(128)
void attn_mma()
{
    const int s    = blockIdx.z;
    const int head = blockIdx.y;
    const int bw   = blockIdx.x;
    const int b    = bw >> 10;
    const int win  = bw & 1023;
    const int os   = 1 - s;

    __shared__ __align__(16) float qs[64 * 36];
    __shared__ __align__(16) float ks[64 * 36];
    __shared__ __align__(16) float vs[64 * 36];
    __shared__ __align__(16) float sim[64 * 69];

    const int tid = threadIdx.x;
    const size_t tile = (size_t)PP * HD;
    const size_t qbase = (((((size_t)s  * 3 + 0) * BB + b) * NWIN + win) * NH + head) * tile;
    const size_t kbase = (((((size_t)os * 3 + 1) * BB + b) * NWIN + win) * NH + head) * tile;
    const size_t vbase = (((((size_t)os * 3 + 2) * BB + b) * NWIN + win) * NH + head) * tile;

#pragma unroll
    for (int it = 0; it < 4; ++it) {
        int e = tid * 4 + it * 512;
        int p = e >> 5, d = e & 31;
        float4 vq = *reinterpret_cast<const float4*>(&g_qkv[qbase + e]);
        qs[p*36+d]   = to_tf32(vq.x); qs[p*36+d+1] = to_tf32(vq.y);
        qs[p*36+d+2] = to_tf32(vq.z); qs[p*36+d+3] = to_tf32(vq.w);
        float4 vk = *reinterpret_cast<const float4*>(&g_qkv[kbase + e]);
        ks[p*36+d]   = to_tf32(vk.x); ks[p*36+d+1] = to_tf32(vk.y);
        ks[p*36+d+2] = to_tf32(vk.z); ks[p*36+d+3] = to_tf32(vk.w);
        float4 vv = *reinterpret_cast<const float4*>(&g_qkv[vbase + e]);
        vs[p*36+d]   = to_tf32(vv.x); vs[p*36+d+1] = to_tf32(vv.y);
        vs[p*36+d+2] = to_tf32(vv.z); vs[p*36+d+3] = to_tf32(vv.w);
    }
    __syncthreads();

    const int w    = tid >> 5;
    const int lane = tid & 31;
    const int g    = lane >> 2;
    const int t4   = lane & 3;
    const int r0   = w * 16;

    // Phase 1: sim = q @ k^T  (M=64 split across warps, N=64, K=32)
    float c1[8][4];
#pragma unroll
    for (int nj = 0; nj < 8; nj++)
#pragma unroll
        for (int k = 0; k < 4; k++) c1[nj][k] = 0.f;

#pragma unroll
    for (int kk = 0; kk < 4; ++kk) {
        int k0 = kk * 8;
        float a0 = qs[(r0 + g) * 36 + k0 + t4];
        float a1 = qs[(r0 + g + 8) * 36 + k0 + t4];
        float a2 = qs[(r0 + g) * 36 + k0 + t4 + 4];
        float a3 = qs[(r0 + g + 8) * 36 + k0 + t4 + 4];
#pragma unroll
        for (int nj = 0; nj < 8; nj++) {
            int n = nj * 8 + g;
            float b0 = ks[n * 36 + k0 + t4];
            float b1 = ks[n * 36 + k0 + t4 + 4];
            mma_tf32_16n8k8(c1[nj], a0, a1, a2, a3, b0, b1);
        }
    }

    // scale + bias + mask -> sim smem
    const size_t bbias = ((size_t)s * NH + head) * 4096;
    const bool mh = ((win >> 5) == 31);
    const bool mw = ((win & 31) == 31);
    const float scale = 0.17677669529663687f;
#pragma unroll
    for (int nj = 0; nj < 8; nj++) {
#pragma unroll
        for (int h2 = 0; h2 < 2; h2++) {
            int row = r0 + g + 8 * h2;
            int col = nj * 8 + t4 * 2;
            float2 bias = *reinterpret_cast<const float2*>(&g_bias[bbias + row * 64 + col]);
            float v0 = c1[nj][h2 * 2 + 0] * scale + bias.x;
            float v1 = c1[nj][h2 * 2 + 1] * scale + bias.y;
            int ip = row >> 3, jp = row & 7;
            int iq = col >> 3;
            int jq0 = col & 7, jq1 = (col + 1) & 7;
            bool m0 = (mh && ((ip < 4) != (iq < 4))) || (mw && ((jp < 4) != (jq0 < 4)));
            bool m1 = (mh && ((ip < 4) != (iq < 4))) || (mw && ((jp < 4) != (jq1 < 4)));
            sim[row * 69 + col]     = m0 ? -1e30f : v0;
            sim[row * 69 + col + 1] = m1 ? -1e30f : v1;
        }
    }
    __syncthreads();

    // Softmax per row, write tf32-rounded probabilities
    if (tid < 64) {
        float* sr = &sim[tid * 69];
        float m = -1e30f;
#pragma unroll 8
        for (int q = 0; q < 64; ++q) m = fmaxf(m, sr[q]);
        float sum = 0.f;
#pragma unroll 8
        for (int q = 0; q < 64; ++q) {
            float e = __expf(sr[q] - m);
            sr[q] = e;
            sum += e;
        }
        float inv = 1.f / sum;
#pragma unroll 8
        for (int q = 0; q < 64; ++q) sr[q] = to_tf32(sr[q] * inv);
    }
    __syncthreads();

    // Phase 2: o = P @ V  (M=64 split, N=32, K=64)
    float c2[4][4];
#pragma unroll
    for (int nj = 0; nj < 4; nj++)
#pragma unroll
        for (int k = 0; k < 4; k++) c2[nj][k] = 0.f;

#pragma unroll
    for (int kk = 0; kk < 8; ++kk) {
        int k0 = kk * 8;
        float a0 = sim[(r0 + g) * 69 + k0 + t4];
        float a1 = sim[(r0 + g + 8) * 69 + k0 + t4];
        float a2 = sim[(r0 + g) * 69 + k0 + t4 + 4];
        float a3 = sim[(r0 + g + 8) * 69 + k0 + t4 + 4];
#pragma unroll
        for (int nj = 0; nj < 4; nj++) {
            int n = nj * 8 + g;
            float b0 = vs[(k0 + t4) * 36 + n];
            float b1 = vs[(k0 + t4 + 4) * 36 + n];
            mma_tf32_16n8k8(c2[nj], a0, a1, a2, a3, b0, b1);
        }
    }

    // Write o to g_attn [s][b][win][p][head*32 + d]
    const size_t obase = (size_t)s * ((size_t)BB * NWIN * PP * CC)
                       + (((size_t)b * NWIN + win) * PP) * CC
                       + (size_t)head * HD;
#pragma unroll
    for (int nj = 0; nj < 4; nj++) {
#pragma unroll
        for (int h2 = 0; h2 < 2; h2++) {
            int row = r0 + g + 8 * h2;
            int col = nj * 8 + t4 * 2;
            float2 v = make_float2(c2[nj][h2 * 2 + 0], c2[nj][h2 * 2 + 1]);
            *reinterpret_cast<float2*>(&g_attn[obase + (size_t)row * CC + col]) = v;
        }
    }
}

// ---------------------------------------------------------------------------
// Kernel 3: output projection (tf32 mma, v2 fragment loads) + unwindow+roll.
// ---------------------------------------------------------------------------
__global__ __launch_bounds__(256)
void proj_mma(const float* __restrict__ bo1, const float* __restrict__ bo2,
              float* __restrict__ out)
{
    __shared__ __align__(16) float As2[128 * AP2];
    __shared__ __align__(16) float Bs2[16 * BROW];

    const int s = blockIdx.z;
    const float* __restrict__ bo = s ? bo2 : bo1;
    float* __restrict__ dst = out + (size_t)s * ((size_t)BB * HH * WW * OUTC);
    const int colBlock = blockIdx.x;     // 0..1
    const int rowBlock = blockIdx.y;     // 0..1023
    const int tid  = threadIdx.x;
    const int wid  = tid >> 5;
    const int lane = tid & 31;
    const int g    = lane >> 2;
    const int t4   = lane & 3;

    const int arow = tid >> 1;
    const int acol = (tid & 1) * 16;
    const int kkbase = acol >> 3;
    const float* aRow = g_attn + (size_t)s * ((size_t)BB * NWIN * PP * CC)
                      + (size_t)(rowBlock * 128 + arow) * CC;

    const float4* wp4 = reinterpret_cast<const float4*>(g_wpack)
                      + 98304 + (size_t)(s * 2 + colBlock) * 8192;

    const int wrb = (wid & 3) * 32;
    const int wcb = (wid >> 2) * 64;

    float acc[2][8][4];
#pragma unroll
    for (int mi = 0; mi < 2; mi++)
#pragma unroll
        for (int nj = 0; nj < 8; nj++)
#pragma unroll
            for (int k = 0; k < 4; k++) acc[mi][nj][k] = 0.f;

    float4 aPre[4], bPre[4];
#pragma unroll
    for (int j = 0; j < 4; ++j) {
        aPre[j] = *reinterpret_cast<const float4*>(aRow + acol + j * 4);
        bPre[j] = wp4[tid + j * 256];
    }

    for (int c = 0; c < 8; ++c) {
        {
            float* dst0 = &As2[arow * AP2 + kkbase * 8];
            float* dst1 = dst0 + 8;
            float2 v;
            v.x = to_tf32(aPre[0].x); v.y = to_tf32(aPre[1].x);
            *reinterpret_cast<float2*>(dst0 + 0) = v;
            v.x = to_tf32(aPre[0].y); v.y = to_tf32(aPre[1].y);
            *reinterpret_cast<float2*>(dst0 + 2) = v;
            v.x = to_tf32(aPre[0].z); v.y = to_tf32(aPre[1].z);
            *reinterpret_cast<float2*>(dst0 + 4) = v;
            v.x = to_tf32(aPre[0].w); v.y = to_tf32(aPre[1].w);
            *reinterpret_cast<float2*>(dst0 + 6) = v;
            v.x = to_tf32(aPre[2].x); v.y = to_tf32(aPre[3].x);
            *reinterpret_cast<float2*>(dst1 + 0) = v;
            v.x = to_tf32(aPre[2].y); v.y = to_tf32(aPre[3].y);
            *reinterpret_cast<float2*>(dst1 + 2) = v;
            v.x = to_tf32(aPre[2].z); v.y = to_tf32(aPre[3].z);
            *reinterpret_cast<float2*>(dst1 + 4) = v;
            v.x = to_tf32(aPre[2].w); v.y = to_tf32(aPre[3].w);
            *reinterpret_cast<float2*>(dst1 + 6) = v;
        }
#pragma unroll
        for (int i = 0; i < 4; ++i) {
            int v = tid + i * 256;
            *reinterpret_cast<float4*>(&Bs2[(v >> 6) * BROW + (v & 63) * 4]) = bPre[i];
        }
        __syncthreads();
        if (c < 7) {
            int k0n = (c + 1) * 32;
#pragma unroll
            for (int j = 0; j < 4; ++j) {
                aPre[j] = *reinterpret_cast<const float4*>(aRow + k0n + acol + j * 4);
                bPre[j] = wp4[(size_t)(c + 1) * 1024 + tid + j * 256];
            }
        }
#pragma unroll
        for (int kk = 0; kk < 4; ++kk) {
            float a[2][4];
#pragma unroll
            for (int mi = 0; mi < 2; mi++) {
                int r0 = wrb + mi * 16 + g;
                float2 lo = *reinterpret_cast<const float2*>(&As2[r0 * AP2 + kk * 8 + t4 * 2]);
                float2 hi = *reinterpret_cast<const float2*>(&As2[(r0 + 8) * AP2 + kk * 8 + t4 * 2]);
                a[mi][0] = lo.x; a[mi][1] = hi.x; a[mi][2] = lo.y; a[mi][3] = hi.y;
            }
            const float* brow = &Bs2[(kk * 4 + t4) * BROW];
#pragma unroll
            for (int nj = 0; nj < 8; nj++) {
                int n = wcb + nj * 8 + g;
                float2 b = *reinterpret_cast<const float2*>(brow + n * 2);
#pragma unroll
                for (int mi = 0; mi < 2; mi++)
                    mma_tf32_16n8k8(acc[mi][nj],
                                    a[mi][0], a[mi][1], a[mi][2], a[mi][3],
                                    b.x, b.y);
            }
        }
        __syncthreads();
    }

    // Epilogue: unwindow + roll scatter
#pragma unroll
    for (int mi = 0; mi < 2; mi++) {
#pragma unroll
        for (int h = 0; h < 2; h++) {
            int r  = rowBlock * 128 + wrb + mi * 16 + g + 8 * h;
            int pr = r & 63, wr = (r >> 6) & 1023, br = r >> 16;
            int hout = (((wr >> 5) << 3) + (pr >> 3) + SHIFT) & 255;
            int wout = ((wr & 31) << 3) + (pr & 7);
            size_t rowbase = (((size_t)br * HH + hout) * WW + wout) * OUTC;
#pragma unroll
            for (int nj = 0; nj < 8; nj++) {
                int n = colBlock * 128 + wcb + nj * 8 + t4 * 2;
                float2 v;
                v.x = acc[mi][nj][h * 2 + 0] + bo[n];
                v.y = acc[mi][nj][h * 2 + 1] + bo[n + 1];
                *reinterpret_cast<float2*>(&dst[rowbase + n]) = v;
            }
        }
    }
}

// ---------------------------------------------------------------------------
// Launch
// ---------------------------------------------------------------------------
extern "C" void kernel_launch(void* const* d_in, const int* in_sizes, int n_in,
                              void* d_out, int out_size)
{
    const float* emb1  = (const float*)d_in[0];
    const float* emb2  = (const float*)d_in[1];
    const float* Wqkv1 = (const float*)d_in[2];
    const float* bqkv1 = (const float*)d_in[3];
    const float* Wqkv2 = (const float*)d_in[4];
    const float* bqkv2 = (const float*)d_in[5];
    const float* rel1  = (const float*)d_in[6];
    const float* rel2  = (const float*)d_in[7];
    const float* Wo1   = (const float*)d_in[8];
    const float* bo1   = (const float*)d_in[9];
    const float* Wo2   = (const float*)d_in[10];
    const float* bo2   = (const float*)d_in[11];
    float* out = (float*)d_out;
    (void)in_sizes; (void)n_in; (void)out_size;

    bias_kernel<<<256, 256>>>(rel1, rel2);
    wpack_kernel<<<2048, 256>>>(Wqkv1, Wqkv2, Wo1, Wo2);

    dim3 gq(6, 1024, 2);
    qkv_mma<<<gq, 256>>>(emb1, emb2, bqkv1, bqkv2);

    dim3 ga(2048, 8, 2);
    attn_mma<<<ga, 128>>>();

    dim3 gp(2, 1024, 2);
    proj_mma<<<gp, 256>>>(bo1, bo2, out);
}

// round 10
// speedup vs baseline: 3.0224x; 1.3454x over previous
#include <cuda_runtime.h>
#include <cuda_fp16.h>
#include <cstdint>

// Problem constants
#define BB 2
#define HH 256
#define WW 256
#define CC 256
#define WS 8
#define SHIFT 4
#define NH 8
#define HD 32
#define OUTC 256
#define NWIN 1024
#define PP 64
#define MROWS 131072

// Scratch (device globals)
__device__ __half g_qkvh[2u*3u*BB*NWIN*NH*PP*HD];   // [s][qkv][b][win][head][p][d] fp16
__device__ __half g_attnh[2u*BB*NWIN*PP*CC];        // [s][b][win][p][C] fp16
__device__ float  g_bias[2*NH*PP*PP];
// Packed fp16 weights, [n][k]-major per (s,cb,kc): qkv 12*32768, proj 4*32768 halves
__device__ __half g_wh[524288];

__device__ __forceinline__ uint32_t f22u(float a, float b) {
    __half2 h = __floats2half2_rn(a, b);
    return *reinterpret_cast<uint32_t*>(&h);
}

__device__ __forceinline__ void mma_f16(float c[4],
                                        uint32_t a0, uint32_t a1, uint32_t a2, uint32_t a3,
                                        uint32_t b0, uint32_t b1) {
    asm volatile(
        "mma.sync.aligned.m16n8k16.row.col.f32.f16.f16.f32 "
        "{%0,%1,%2,%3}, {%4,%5,%6,%7}, {%8,%9}, {%0,%1,%2,%3};"
        : "+f"(c[0]), "+f"(c[1]), "+f"(c[2]), "+f"(c[3])
        : "r"(a0), "r"(a1), "r"(a2), "r"(a3), "r"(b0), "r"(b1));
}

#define APH 40    // half pitch for A/B smem tiles (conflict-free: 20g+t4 pattern)

// ---------------------------------------------------------------------------
// Kernel 0a: bias table
// ---------------------------------------------------------------------------
__global__ void bias_kernel(const float* __restrict__ rel1,
                            const float* __restrict__ rel2)
{
    int idx = blockIdx.x * blockDim.x + threadIdx.x;
    int s = idx >> 15, head = (idx >> 12) & 7, p = (idx >> 6) & 63, q = idx & 63;
    const float* rel = s ? rel2 : rel1;
    int a = (p >> 3) - (q >> 3) + 7;
    int b = (p & 7) - (q & 7) + 7;
    g_bias[idx] = rel[head * 225 + a * 15 + b];
}

// ---------------------------------------------------------------------------
// Kernel 0b: pack weights into fp16 [kc][n][k] layout per (s,cb)
// ---------------------------------------------------------------------------
__global__ void wpack_kernel(const float* __restrict__ Wqkv1,
                             const float* __restrict__ Wqkv2,
                             const float* __restrict__ Wo1,
                             const float* __restrict__ Wo2)
{
    int idx = blockIdx.x * blockDim.x + threadIdx.x;   // 0..524287
    const float* W;
    int N, cb, r;
    if (idx < 393216) {
        int scb = idx >> 15;            // 0..11
        r = idx & 32767;
        int s = scb / 6; cb = scb % 6;
        W = s ? Wqkv2 : Wqkv1; N = 768;
    } else {
        int t = idx - 393216;
        int scb = t >> 15;              // 0..3
        r = t & 32767;
        int s = scb >> 1; cb = scb & 1;
        W = s ? Wo2 : Wo1; N = 256;
    }
    int kc = r >> 12;
    int r2 = r & 4095;
    int nl = r2 >> 5, kk = r2 & 31;
    int k = kc * 32 + kk;
    int n = cb * 128 + nl;
    g_wh[idx] = __float2half_rn(W[k * N + n]);
}

// ---------------------------------------------------------------------------
// Kernel 1: QKV GEMM (fp16 m16n8k16).  M=131072, N=768, K=256 per stream.
// 128x128 tile, 8 warps (32x64 warp tile), K chunks of 32.
// ---------------------------------------------------------------------------
__global__ __launch_bounds__(256)
void qkv_mma(const float* __restrict__ emb1, const float* __restrict__ emb2,
             const float* __restrict__ bqkv1, const float* __restrict__ bqkv2)
{
    __shared__ __align__(16) __half As[128 * APH];
    __shared__ __align__(16) __half Bs[128 * APH];

    const int s = blockIdx.z;
    const float* __restrict__ emb = s ? emb2 : emb1;
    const float* __restrict__ bq  = s ? bqkv2 : bqkv1;
    const int colBlock = blockIdx.x;     // 0..5
    const int rowBlock = blockIdx.y;     // 0..1023
    const int tid  = threadIdx.x;
    const int wid  = tid >> 5;
    const int lane = tid & 31;
    const int g    = lane >> 2;
    const int t4   = lane & 3;

    // A loader: row tid>>1 (0..127), k-halves (tid&1)*16 .. +15 per chunk
    const int arow = tid >> 1;
    const int apart = tid & 1;
    const int acol = apart * 16;
    int R = rowBlock * 128 + arow;
    int p_ = R & 63, win_ = (R >> 6) & 1023, b_ = R >> 16;
    int hs = (((win_ >> 5) << 3) + (p_ >> 3) + SHIFT) & 255;
    int wsrc = ((win_ & 31) << 3) + (p_ & 7);
    const float* aRow = emb + ((((size_t)b_ * HH + hs) * WW + wsrc) * CC);

    // B loader: n = tid>>1 (0..127), k-halves (tid&1)*16 per chunk
    const uint4* wb4 = reinterpret_cast<const uint4*>(
        g_wh + (size_t)(s * 6 + colBlock) * 32768);
    const int bidx0 = (tid >> 1) * 4 + apart * 2;

    const int wrb = (wid & 3) * 32;
    const int wcb = (wid >> 2) * 64;

    float acc[2][8][4];
#pragma unroll
    for (int mi = 0; mi < 2; mi++)
#pragma unroll
        for (int nj = 0; nj < 8; nj++)
#pragma unroll
            for (int k = 0; k < 4; k++) acc[mi][nj][k] = 0.f;

    float4 aPre[4];
    uint4  bPre[2];
#pragma unroll
    for (int j = 0; j < 4; ++j)
        aPre[j] = *reinterpret_cast<const float4*>(aRow + acol + j * 4);
    bPre[0] = wb4[bidx0]; bPre[1] = wb4[bidx0 + 1];

    for (int c = 0; c < 8; ++c) {
        // A store (convert to fp16)
        {
            uint4 u0, u1;
            u0.x = f22u(aPre[0].x, aPre[0].y); u0.y = f22u(aPre[0].z, aPre[0].w);
            u0.z = f22u(aPre[1].x, aPre[1].y); u0.w = f22u(aPre[1].z, aPre[1].w);
            u1.x = f22u(aPre[2].x, aPre[2].y); u1.y = f22u(aPre[2].z, aPre[2].w);
            u1.z = f22u(aPre[3].x, aPre[3].y); u1.w = f22u(aPre[3].z, aPre[3].w);
            *reinterpret_cast<uint4*>(&As[arow * APH + acol])     = u0;
            *reinterpret_cast<uint4*>(&As[arow * APH + acol + 8]) = u1;
        }
        // B store (already fp16 [n][k])
        *reinterpret_cast<uint4*>(&Bs[(tid >> 1) * APH + acol])     = bPre[0];
        *reinterpret_cast<uint4*>(&Bs[(tid >> 1) * APH + acol + 8]) = bPre[1];
        __syncthreads();
        if (c < 7) {
            int k0n = (c + 1) * 32;
#pragma unroll
            for (int j = 0; j < 4; ++j)
                aPre[j] = *reinterpret_cast<const float4*>(aRow + k0n + acol + j * 4);
            bPre[0] = wb4[(c + 1) * 512 + bidx0];
            bPre[1] = wb4[(c + 1) * 512 + bidx0 + 1];
        }
#pragma unroll
        for (int k16 = 0; k16 < 2; ++k16) {
            int kb = k16 * 16 + 2 * t4;
            uint32_t a[2][4];
#pragma unroll
            for (int mi = 0; mi < 2; mi++) {
                int r0 = wrb + mi * 16 + g;
                a[mi][0] = *reinterpret_cast<const uint32_t*>(&As[r0 * APH + kb]);
                a[mi][1] = *reinterpret_cast<const uint32_t*>(&As[(r0 + 8) * APH + kb]);
                a[mi][2] = *reinterpret_cast<const uint32_t*>(&As[r0 * APH + kb + 8]);
                a[mi][3] = *reinterpret_cast<const uint32_t*>(&As[(r0 + 8) * APH + kb + 8]);
            }
#pragma unroll
            for (int nj = 0; nj < 8; nj++) {
                int n = wcb + nj * 8 + g;
                uint32_t b0 = *reinterpret_cast<const uint32_t*>(&Bs[n * APH + kb]);
                uint32_t b1 = *reinterpret_cast<const uint32_t*>(&Bs[n * APH + kb + 8]);
                mma_f16(acc[0][nj], a[0][0], a[0][1], a[0][2], a[0][3], b0, b1);
                mma_f16(acc[1][nj], a[1][0], a[1][1], a[1][2], a[1][3], b0, b1);
            }
        }
        __syncthreads();
    }

    // Epilogue: add bias, convert fp16, scatter to q/k/v layout
#pragma unroll
    for (int mi = 0; mi < 2; mi++) {
#pragma unroll
        for (int h = 0; h < 2; h++) {
            int r  = rowBlock * 128 + wrb + mi * 16 + g + 8 * h;
            int pr = r & 63, wr = (r >> 6) & 1023, br = r >> 16;
#pragma unroll
            for (int nj = 0; nj < 8; nj++) {
                int n = colBlock * 128 + wcb + nj * 8 + t4 * 2;
                float vx = acc[mi][nj][h * 2 + 0] + bq[n];
                float vy = acc[mi][nj][h * 2 + 1] + bq[n + 1];
                int qkvi = n >> 8, head = (n >> 5) & 7, d = n & 31;
                size_t idx = ((((size_t)(s * 3 + qkvi) * BB + br) * NWIN + wr) * NH + head)
                                 * ((size_t)PP * HD)
                             + (size_t)pr * HD + d;
                __half2 hv = __floats2half2_rn(vx, vy);
                *reinterpret_cast<__half2*>(&g_qkvh[idx]) = hv;
            }
        }
    }
}

// ---------------------------------------------------------------------------
// Kernel 2: windowed cross-attention, fp16 mma. Block=(b*win, head, s),
// 128 threads = 4 warps x 16 rows.
// ---------------------------------------------------------------------------
__global__ __launch_bounds__(128)
void attn_mma()
{
    const int s    = blockIdx.z;
    const int head = blockIdx.y;
    const int bw   = blockIdx.x;
    const int b    = bw >> 10;
    const int win  = bw & 1023;
    const int os   = 1 - s;

    __shared__ __align__(16) __half qs[64 * APH];
    __shared__ __align__(16) __half ks[64 * APH];
    __shared__ __align__(16) __half vsT[32 * 72];   // transposed [d][p]
    __shared__ __align__(16) float  sim[64 * 69];
    __shared__ __align__(16) __half Ps[64 * 72];

    const int tid = threadIdx.x;
    const size_t tile = (size_t)PP * HD;
    const size_t qbase = (((((size_t)s  * 3 + 0) * BB + b) * NWIN + win) * NH + head) * tile;
    const size_t kbase = (((((size_t)os * 3 + 1) * BB + b) * NWIN + win) * NH + head) * tile;
    const size_t vbase = (((((size_t)os * 3 + 2) * BB + b) * NWIN + win) * NH + head) * tile;

    // Loaders: thread t covers halves t*16..t*16+15 (p = t>>1, d0 = (t&1)*16)
    {
        const uint4* qg = reinterpret_cast<const uint4*>(&g_qkvh[qbase]);
        const uint4* kg = reinterpret_cast<const uint4*>(&g_qkvh[kbase]);
        const uint4* vg = reinterpret_cast<const uint4*>(&g_qkvh[vbase]);
        int u  = tid * 2;
        int p  = tid >> 1;
        int d0 = (tid & 1) * 16;
        uint4 x0 = qg[u], x1 = qg[u + 1];
        *reinterpret_cast<uint4*>(&qs[p * APH + d0])     = x0;
        *reinterpret_cast<uint4*>(&qs[p * APH + d0 + 8]) = x1;
        uint4 y0 = kg[u], y1 = kg[u + 1];
        *reinterpret_cast<uint4*>(&ks[p * APH + d0])     = y0;
        *reinterpret_cast<uint4*>(&ks[p * APH + d0 + 8]) = y1;
        union { uint4 v4[2]; __half h[16]; } tv;
        tv.v4[0] = vg[u]; tv.v4[1] = vg[u + 1];
#pragma unroll
        for (int j = 0; j < 16; ++j)
            vsT[(d0 + j) * 72 + p] = tv.h[j];
    }
    __syncthreads();

    const int w    = tid >> 5;
    const int lane = tid & 31;
    const int g    = lane >> 2;
    const int t4   = lane & 3;
    const int r0   = w * 16;

    // Phase 1: sim = q @ k^T  (M=16/warp, N=64, K=32)
    float c1[8][4];
#pragma unroll
    for (int nj = 0; nj < 8; nj++)
#pragma unroll
        for (int k = 0; k < 4; k++) c1[nj][k] = 0.f;

#pragma unroll
    for (int k16 = 0; k16 < 2; ++k16) {
        int kb = k16 * 16 + 2 * t4;
        uint32_t a0 = *reinterpret_cast<const uint32_t*>(&qs[(r0 + g) * APH + kb]);
        uint32_t a1 = *reinterpret_cast<const uint32_t*>(&qs[(r0 + g + 8) * APH + kb]);
        uint32_t a2 = *reinterpret_cast<const uint32_t*>(&qs[(r0 + g) * APH + kb + 8]);
        uint32_t a3 = *reinterpret_cast<const uint32_t*>(&qs[(r0 + g + 8) * APH + kb + 8]);
#pragma unroll
        for (int nj = 0; nj < 8; nj++) {
            int n = nj * 8 + g;
            uint32_t b0 = *reinterpret_cast<const uint32_t*>(&ks[n * APH + kb]);
            uint32_t b1 = *reinterpret_cast<const uint32_t*>(&ks[n * APH + kb + 8]);
            mma_f16(c1[nj], a0, a1, a2, a3, b0, b1);
        }
    }

    // scale + bias + mask -> sim smem (fp32)
    const size_t bbias = ((size_t)s * NH + head) * 4096;
    const bool mh = ((win >> 5) == 31);
    const bool mw = ((win & 31) == 31);
    const float scale = 0.17677669529663687f;
#pragma unroll
    for (int nj = 0; nj < 8; nj++) {
#pragma unroll
        for (int h2 = 0; h2 < 2; h2++) {
            int row = r0 + g + 8 * h2;
            int col = nj * 8 + t4 * 2;
            float2 bias = *reinterpret_cast<const float2*>(&g_bias[bbias + row * 64 + col]);
            float v0 = c1[nj][h2 * 2 + 0] * scale + bias.x;
            float v1 = c1[nj][h2 * 2 + 1] * scale + bias.y;
            int ip = row >> 3, jp = row & 7;
            int iq = col >> 3;
            int jq0 = col & 7, jq1 = (col + 1) & 7;
            bool m0 = (mh && ((ip < 4) != (iq < 4))) || (mw && ((jp < 4) != (jq0 < 4)));
            bool m1 = (mh && ((ip < 4) != (iq < 4))) || (mw && ((jp < 4) != (jq1 < 4)));
            sim[row * 69 + col]     = m0 ? -1e30f : v0;
            sim[row * 69 + col + 1] = m1 ? -1e30f : v1;
        }
    }
    __syncthreads();

    // Softmax per row (fp32)
    if (tid < 64) {
        float* sr = &sim[tid * 69];
        float m = -1e30f;
#pragma unroll 8
        for (int q = 0; q < 64; ++q) m = fmaxf(m, sr[q]);
        float sum = 0.f;
#pragma unroll 8
        for (int q = 0; q < 64; ++q) {
            float e = __expf(sr[q] - m);
            sr[q] = e;
            sum += e;
        }
        float inv = 1.f / sum;
#pragma unroll 8
        for (int q = 0; q < 64; ++q) sr[q] *= inv;
    }
    __syncthreads();

    // Convert P to fp16 (2 threads per row)
    {
        int row = tid >> 1;
        int c0  = (tid & 1) * 32;
        const float* sr = &sim[row * 69 + c0];
#pragma unroll
        for (int q = 0; q < 32; q += 2)
            *reinterpret_cast<uint32_t*>(&Ps[row * 72 + c0 + q]) = f22u(sr[q], sr[q + 1]);
    }
    __syncthreads();

    // Phase 2: o = P @ V  (M=16/warp, N=32, K=64)
    float c2[4][4];
#pragma unroll
    for (int nj = 0; nj < 4; nj++)
#pragma unroll
        for (int k = 0; k < 4; k++) c2[nj][k] = 0.f;

#pragma unroll
    for (int k16 = 0; k16 < 4; ++k16) {
        int kb = k16 * 16 + 2 * t4;
        uint32_t a0 = *reinterpret_cast<const uint32_t*>(&Ps[(r0 + g) * 72 + kb]);
        uint32_t a1 = *reinterpret_cast<const uint32_t*>(&Ps[(r0 + g + 8) * 72 + kb]);
        uint32_t a2 = *reinterpret_cast<const uint32_t*>(&Ps[(r0 + g) * 72 + kb + 8]);
        uint32_t a3 = *reinterpret_cast<const uint32_t*>(&Ps[(r0 + g + 8) * 72 + kb + 8]);
#pragma unroll
        for (int nj = 0; nj < 4; nj++) {
            int n = nj * 8 + g;
            uint32_t b0 = *reinterpret_cast<const uint32_t*>(&vsT[n * 72 + kb]);
            uint32_t b1 = *reinterpret_cast<const uint32_t*>(&vsT[n * 72 + kb + 8]);
            mma_f16(c2[nj], a0, a1, a2, a3, b0, b1);
        }
    }

    // Write o (fp16) to g_attnh [s][b][win][p][head*32 + d]
    const size_t obase = (size_t)s * ((size_t)BB * NWIN * PP * CC)
                       + (((size_t)b * NWIN + win) * PP) * CC
                       + (size_t)head * HD;
#pragma unroll
    for (int nj = 0; nj < 4; nj++) {
#pragma unroll
        for (int h2 = 0; h2 < 2; h2++) {
            int row = r0 + g + 8 * h2;
            int col = nj * 8 + t4 * 2;
            __half2 hv = __floats2half2_rn(c2[nj][h2 * 2 + 0], c2[nj][h2 * 2 + 1]);
            *reinterpret_cast<__half2*>(&g_attnh[obase + (size_t)row * CC + col]) = hv;
        }
    }
}

// ---------------------------------------------------------------------------
// Kernel 3: output projection (fp16 mma) + unwindow + roll scatter.
// ---------------------------------------------------------------------------
__global__ __launch_bounds__(256)
void proj_mma(const float* __restrict__ bo1, const float* __restrict__ bo2,
              float* __restrict__ out)
{
    __shared__ __align__(16) __half As[128 * APH];
    __shared__ __align__(16) __half Bs[128 * APH];

    const int s = blockIdx.z;
    const float* __restrict__ bo = s ? bo2 : bo1;
    float* __restrict__ dst = out + (size_t)s * ((size_t)BB * HH * WW * OUTC);
    const int colBlock = blockIdx.x;     // 0..1
    const int rowBlock = blockIdx.y;     // 0..1023
    const int tid  = threadIdx.x;
    const int wid  = tid >> 5;
    const int lane = tid & 31;
    const int g    = lane >> 2;
    const int t4   = lane & 3;

    const int arow  = tid >> 1;
    const int apart = tid & 1;
    const int acol  = apart * 16;
    // A row in g_attnh: 256 halves = 32 uint4
    const uint4* aR = reinterpret_cast<const uint4*>(
        g_attnh + (size_t)s * ((size_t)BB * NWIN * PP * CC)
                + (size_t)(rowBlock * 128 + arow) * CC);

    const uint4* wb4 = reinterpret_cast<const uint4*>(
        g_wh + 393216 + (size_t)(s * 2 + colBlock) * 32768);
    const int bidx0 = (tid >> 1) * 4 + apart * 2;

    const int wrb = (wid & 3) * 32;
    const int wcb = (wid >> 2) * 64;

    float acc[2][8][4];
#pragma unroll
    for (int mi = 0; mi < 2; mi++)
#pragma unroll
        for (int nj = 0; nj < 8; nj++)
#pragma unroll
            for (int k = 0; k < 4; k++) acc[mi][nj][k] = 0.f;

    uint4 aPre[2], bPre[2];
    aPre[0] = aR[apart * 2];     aPre[1] = aR[apart * 2 + 1];
    bPre[0] = wb4[bidx0];        bPre[1] = wb4[bidx0 + 1];

    for (int c = 0; c < 8; ++c) {
        *reinterpret_cast<uint4*>(&As[arow * APH + acol])     = aPre[0];
        *reinterpret_cast<uint4*>(&As[arow * APH + acol + 8]) = aPre[1];
        *reinterpret_cast<uint4*>(&Bs[(tid >> 1) * APH + acol])     = bPre[0];
        *reinterpret_cast<uint4*>(&Bs[(tid >> 1) * APH + acol + 8]) = bPre[1];
        __syncthreads();
        if (c < 7) {
            aPre[0] = aR[(c + 1) * 4 + apart * 2];
            aPre[1] = aR[(c + 1) * 4 + apart * 2 + 1];
            bPre[0] = wb4[(c + 1) * 512 + bidx0];
            bPre[1] = wb4[(c + 1) * 512 + bidx0 + 1];
        }
#pragma unroll
        for (int k16 = 0; k16 < 2; ++k16) {
            int kb = k16 * 16 + 2 * t4;
            uint32_t a[2][4];
#pragma unroll
            for (int mi = 0; mi < 2; mi++) {
                int r0 = wrb + mi * 16 + g;
                a[mi][0] = *reinterpret_cast<const uint32_t*>(&As[r0 * APH + kb]);
                a[mi][1] = *reinterpret_cast<const uint32_t*>(&As[(r0 + 8) * APH + kb]);
                a[mi][2] = *reinterpret_cast<const uint32_t*>(&As[r0 * APH + kb + 8]);
                a[mi][3] = *reinterpret_cast<const uint32_t*>(&As[(r0 + 8) * APH + kb + 8]);
            }
#pragma unroll
            for (int nj = 0; nj < 8; nj++) {
                int n = wcb + nj * 8 + g;
                uint32_t b0 = *reinterpret_cast<const uint32_t*>(&Bs[n * APH + kb]);
                uint32_t b1 = *reinterpret_cast<const uint32_t*>(&Bs[n * APH + kb + 8]);
                mma_f16(acc[0][nj], a[0][0], a[0][1], a[0][2], a[0][3], b0, b1);
                mma_f16(acc[1][nj], a[1][0], a[1][1], a[1][2], a[1][3], b0, b1);
            }
        }
        __syncthreads();
    }

    // Epilogue: unwindow + roll scatter (fp32 output)
#pragma unroll
    for (int mi = 0; mi < 2; mi++) {
#pragma unroll
        for (int h = 0; h < 2; h++) {
            int r  = rowBlock * 128 + wrb + mi * 16 + g + 8 * h;
            int pr = r & 63, wr = (r >> 6) & 1023, br = r >> 16;
            int hout = (((wr >> 5) << 3) + (pr >> 3) + SHIFT) & 255;
            int wout = ((wr & 31) << 3) + (pr & 7);
            size_t rowbase = (((size_t)br * HH + hout) * WW + wout) * OUTC;
#pragma unroll
            for (int nj = 0; nj < 8; nj++) {
                int n = colBlock * 128 + wcb + nj * 8 + t4 * 2;
                float2 v;
                v.x = acc[mi][nj][h * 2 + 0] + bo[n];
                v.y = acc[mi][nj][h * 2 + 1] + bo[n + 1];
                *reinterpret_cast<float2*>(&dst[rowbase + n]) = v;
            }
        }
    }
}

// ---------------------------------------------------------------------------
// Launch
// ---------------------------------------------------------------------------
extern "C" void kernel_launch(void* const* d_in, const int* in_sizes, int n_in,
                              void* d_out, int out_size)
{
    const float* emb1  = (const float*)d_in[0];
    const float* emb2  = (const float*)d_in[1];
    const float* Wqkv1 = (const float*)d_in[2];
    const float* bqkv1 = (const float*)d_in[3];
    const float* Wqkv2 = (const float*)d_in[4];
    const float* bqkv2 = (const float*)d_in[5];
    const float* rel1  = (const float*)d_in[6];
    const float* rel2  = (const float*)d_in[7];
    const float* Wo1   = (const float*)d_in[8];
    const float* bo1   = (const float*)d_in[9];
    const float* Wo2   = (const float*)d_in[10];
    const float* bo2   = (const float*)d_in[11];
    float* out = (float*)d_out;
    (void)in_sizes; (void)n_in; (void)out_size;

    bias_kernel<<<256, 256>>>(rel1, rel2);
    wpack_kernel<<<2048, 256>>>(Wqkv1, Wqkv2, Wo1, Wo2);

    dim3 gq(6, 1024, 2);
    qkv_mma<<<gq, 256>>>(emb1, emb2, bqkv1, bqkv2);

    dim3 ga(2048, 8, 2);
    attn_mma<<<ga, 128>>>();

    dim3 gp(2, 1024, 2);
    proj_mma<<<gp, 256>>>(bo1, bo2, out);
}

// round 11
// speedup vs baseline: 3.0687x; 1.0153x over previous
#include <cuda_runtime.h>
#include <cuda_fp16.h>
#include <cstdint>

// Problem constants
#define BB 2
#define HH 256
#define WW 256
#define CC 256
#define WS 8
#define SHIFT 4
#define NH 8
#define HD 32
#define OUTC 256
#define NWIN 1024
#define PP 64
#define MROWS 131072

// Scratch (device globals)
__device__ __half g_qkvh[2u*3u*BB*NWIN*NH*PP*HD];   // [s][qkv][b][win][head][p][d] fp16
__device__ __half g_attnh[2u*BB*NWIN*PP*CC];        // [s][b][win][p][C] fp16
__device__ float  g_bias[2*NH*PP*PP];
__device__ __half g_wh[524288];                     // packed fp16 weights [n][k]

__device__ __forceinline__ uint32_t f22u(float a, float b) {
    __half2 h = __floats2half2_rn(a, b);
    return *reinterpret_cast<uint32_t*>(&h);
}

__device__ __forceinline__ void mma_f16(float c[4],
                                        uint32_t a0, uint32_t a1, uint32_t a2, uint32_t a3,
                                        uint32_t b0, uint32_t b1) {
    asm volatile(
        "mma.sync.aligned.m16n8k16.row.col.f32.f16.f16.f32 "
        "{%0,%1,%2,%3}, {%4,%5,%6,%7}, {%8,%9}, {%0,%1,%2,%3};"
        : "+f"(c[0]), "+f"(c[1]), "+f"(c[2]), "+f"(c[3])
        : "r"(a0), "r"(a1), "r"(a2), "r"(a3), "r"(b0), "r"(b1));
}

__device__ __forceinline__ void ldsm4(uint32_t& r0, uint32_t& r1, uint32_t& r2, uint32_t& r3,
                                      uint32_t addr) {
    asm volatile("ldmatrix.sync.aligned.m8n8.x4.shared.b16 {%0,%1,%2,%3}, [%4];"
                 : "=r"(r0), "=r"(r1), "=r"(r2), "=r"(r3) : "r"(addr));
}
__device__ __forceinline__ void ldsm4t(uint32_t& r0, uint32_t& r1, uint32_t& r2, uint32_t& r3,
                                       uint32_t addr) {
    asm volatile("ldmatrix.sync.aligned.m8n8.x4.trans.shared.b16 {%0,%1,%2,%3}, [%4];"
                 : "=r"(r0), "=r"(r1), "=r"(r2), "=r"(r3) : "r"(addr));
}
__device__ __forceinline__ uint32_t sm_a(const void* p) {
    return (uint32_t)__cvta_generic_to_shared(p);
}

#define APH 40    // half pitch; row stride 80B -> conflict-free ldmatrix

// ---------------------------------------------------------------------------
// Kernel 0a: bias table
// ---------------------------------------------------------------------------
__global__ void bias_kernel(const float* __restrict__ rel1,
                            const float* __restrict__ rel2)
{
    int idx = blockIdx.x * blockDim.x + threadIdx.x;
    int s = idx >> 15, head = (idx >> 12) & 7, p = (idx >> 6) & 63, q = idx & 63;
    const float* rel = s ? rel2 : rel1;
    int a = (p >> 3) - (q >> 3) + 7;
    int b = (p & 7) - (q & 7) + 7;
    g_bias[idx] = rel[head * 225 + a * 15 + b];
}

// ---------------------------------------------------------------------------
// Kernel 0b: pack weights into fp16 [kc][n][k] layout per (s,cb)
// ---------------------------------------------------------------------------
__global__ void wpack_kernel(const float* __restrict__ Wqkv1,
                             const float* __restrict__ Wqkv2,
                             const float* __restrict__ Wo1,
                             const float* __restrict__ Wo2)
{
    int idx = blockIdx.x * blockDim.x + threadIdx.x;   // 0..524287
    const float* W;
    int N, cb, r;
    if (idx < 393216) {
        int scb = idx >> 15;
        r = idx & 32767;
        int s = scb / 6; cb = scb % 6;
        W = s ? Wqkv2 : Wqkv1; N = 768;
    } else {
        int t = idx - 393216;
        int scb = t >> 15;
        r = t & 32767;
        int s = scb >> 1; cb = scb & 1;
        W = s ? Wo2 : Wo1; N = 256;
    }
    int kc = r >> 12;
    int r2 = r & 4095;
    int nl = r2 >> 5, kk = r2 & 31;
    int k = kc * 32 + kk;
    int n = cb * 128 + nl;
    g_wh[idx] = __float2half_rn(W[k * N + n]);
}

// ---------------------------------------------------------------------------
// Kernel 1: QKV GEMM (fp16 m16n8k16 + ldmatrix).  128x128 tile, 8 warps.
// ---------------------------------------------------------------------------
__global__ __launch_bounds__(256)
void qkv_mma(const float* __restrict__ emb1, const float* __restrict__ emb2,
             const float* __restrict__ bqkv1, const float* __restrict__ bqkv2)
{
    __shared__ __align__(16) __half As[128 * APH];
    __shared__ __align__(16) __half Bs[128 * APH];

    const int s = blockIdx.z;
    const float* __restrict__ emb = s ? emb2 : emb1;
    const float* __restrict__ bq  = s ? bqkv2 : bqkv1;
    const int colBlock = blockIdx.x;     // 0..5
    const int rowBlock = blockIdx.y;     // 0..1023
    const int tid  = threadIdx.x;
    const int wid  = tid >> 5;
    const int lane = tid & 31;
    const int g    = lane >> 2;
    const int t4   = lane & 3;

    const int arow = tid >> 1;
    const int apart = tid & 1;
    const int acol = apart * 16;
    int R = rowBlock * 128 + arow;
    int p_ = R & 63, win_ = (R >> 6) & 1023, b_ = R >> 16;
    int hs = (((win_ >> 5) << 3) + (p_ >> 3) + SHIFT) & 255;
    int wsrc = ((win_ & 31) << 3) + (p_ & 7);
    const float* aRow = emb + ((((size_t)b_ * HH + hs) * WW + wsrc) * CC);

    const uint4* wb4 = reinterpret_cast<const uint4*>(
        g_wh + (size_t)(s * 6 + colBlock) * 32768);
    const int bidx0 = (tid >> 1) * 4 + apart * 2;

    const int wrb = (wid & 3) * 32;
    const int wcb = (wid >> 2) * 64;

    // ldmatrix addresses (tile layout: i&1 -> +8 row for A / +8 col for B ...)
    const int lrow = lane & 7;
    // A: tiles 0:(r,kb) 1:(r+8,kb) 2:(r,kb+8) 3:(r+8,kb+8)
    uint32_t aAddr0 = sm_a(&As[(wrb +      lrow + ((lane >> 3) & 1) * 8) * APH + ((lane >> 4) & 1) * 8]);
    uint32_t aAddr1 = sm_a(&As[(wrb + 16 + lrow + ((lane >> 3) & 1) * 8) * APH + ((lane >> 4) & 1) * 8]);
    // B: tiles 0:(n,kb) 1:(n,kb+8) 2:(n+8,kb) 3:(n+8,kb+8)
    uint32_t bAddr  = sm_a(&Bs[(wcb + lrow + ((lane >> 4) & 1) * 8) * APH + ((lane >> 3) & 1) * 8]);

    float acc[2][8][4];
#pragma unroll
    for (int mi = 0; mi < 2; mi++)
#pragma unroll
        for (int nj = 0; nj < 8; nj++)
#pragma unroll
            for (int k = 0; k < 4; k++) acc[mi][nj][k] = 0.f;

    float4 aPre[4];
    uint4  bPre[2];
#pragma unroll
    for (int j = 0; j < 4; ++j)
        aPre[j] = *reinterpret_cast<const float4*>(aRow + acol + j * 4);
    bPre[0] = wb4[bidx0]; bPre[1] = wb4[bidx0 + 1];

    for (int c = 0; c < 8; ++c) {
        {
            uint4 u0, u1;
            u0.x = f22u(aPre[0].x, aPre[0].y); u0.y = f22u(aPre[0].z, aPre[0].w);
            u0.z = f22u(aPre[1].x, aPre[1].y); u0.w = f22u(aPre[1].z, aPre[1].w);
            u1.x = f22u(aPre[2].x, aPre[2].y); u1.y = f22u(aPre[2].z, aPre[2].w);
            u1.z = f22u(aPre[3].x, aPre[3].y); u1.w = f22u(aPre[3].z, aPre[3].w);
            *reinterpret_cast<uint4*>(&As[arow * APH + acol])     = u0;
            *reinterpret_cast<uint4*>(&As[arow * APH + acol + 8]) = u1;
        }
        *reinterpret_cast<uint4*>(&Bs[(tid >> 1) * APH + acol])     = bPre[0];
        *reinterpret_cast<uint4*>(&Bs[(tid >> 1) * APH + acol + 8]) = bPre[1];
        __syncthreads();
        if (c < 7) {
            int k0n = (c + 1) * 32;
#pragma unroll
            for (int j = 0; j < 4; ++j)
                aPre[j] = *reinterpret_cast<const float4*>(aRow + k0n + acol + j * 4);
            bPre[0] = wb4[(c + 1) * 512 + bidx0];
            bPre[1] = wb4[(c + 1) * 512 + bidx0 + 1];
        }
#pragma unroll
        for (int k16 = 0; k16 < 2; ++k16) {
            uint32_t a0[2], a1[2], a2[2], a3[2];
            ldsm4(a0[0], a1[0], a2[0], a3[0], aAddr0 + k16 * 32);
            ldsm4(a0[1], a1[1], a2[1], a3[1], aAddr1 + k16 * 32);
#pragma unroll
            for (int jp = 0; jp < 4; ++jp) {
                uint32_t b00, b10, b01, b11;
                ldsm4(b00, b10, b01, b11, bAddr + jp * (16 * APH * 2) + k16 * 32);
                mma_f16(acc[0][2*jp],   a0[0], a1[0], a2[0], a3[0], b00, b10);
                mma_f16(acc[0][2*jp+1], a0[0], a1[0], a2[0], a3[0], b01, b11);
                mma_f16(acc[1][2*jp],   a0[1], a1[1], a2[1], a3[1], b00, b10);
                mma_f16(acc[1][2*jp+1], a0[1], a1[1], a2[1], a3[1], b01, b11);
            }
        }
        __syncthreads();
    }

    // Epilogue: add bias, convert fp16, scatter to q/k/v layout
#pragma unroll
    for (int mi = 0; mi < 2; mi++) {
#pragma unroll
        for (int h = 0; h < 2; h++) {
            int r  = rowBlock * 128 + wrb + mi * 16 + g + 8 * h;
            int pr = r & 63, wr = (r >> 6) & 1023, br = r >> 16;
#pragma unroll
            for (int nj = 0; nj < 8; nj++) {
                int n = colBlock * 128 + wcb + nj * 8 + t4 * 2;
                float vx = acc[mi][nj][h * 2 + 0] + bq[n];
                float vy = acc[mi][nj][h * 2 + 1] + bq[n + 1];
                int qkvi = n >> 8, head = (n >> 5) & 7, d = n & 31;
                size_t idx = ((((size_t)(s * 3 + qkvi) * BB + br) * NWIN + wr) * NH + head)
                                 * ((size_t)PP * HD)
                             + (size_t)pr * HD + d;
                __half2 hv = __floats2half2_rn(vx, vy);
                *reinterpret_cast<__half2*>(&g_qkvh[idx]) = hv;
            }
        }
    }
}

// ---------------------------------------------------------------------------
// Kernel 2: windowed cross-attention, register softmax + ldmatrix.
// Block=(b*win, head, s), 128 threads = 4 warps x 16 rows.
// ---------------------------------------------------------------------------
__global__ __launch_bounds__(128)
void attn_mma()
{
    const int s    = blockIdx.z;
    const int head = blockIdx.y;
    const int bw   = blockIdx.x;
    const int b    = bw >> 10;
    const int win  = bw & 1023;
    const int os   = 1 - s;

    __shared__ __align__(16) __half qs[64 * APH];
    __shared__ __align__(16) __half ks[64 * APH];
    __shared__ __align__(16) __half vs[64 * APH];   // [p][d]

    const int tid = threadIdx.x;
    const size_t tile = (size_t)PP * HD;
    const size_t qbase = (((((size_t)s  * 3 + 0) * BB + b) * NWIN + win) * NH + head) * tile;
    const size_t kbase = (((((size_t)os * 3 + 1) * BB + b) * NWIN + win) * NH + head) * tile;
    const size_t vbase = (((((size_t)os * 3 + 2) * BB + b) * NWIN + win) * NH + head) * tile;

    {
        const uint4* qg = reinterpret_cast<const uint4*>(&g_qkvh[qbase]);
        const uint4* kg = reinterpret_cast<const uint4*>(&g_qkvh[kbase]);
        const uint4* vg = reinterpret_cast<const uint4*>(&g_qkvh[vbase]);
        int u  = tid * 2;
        int p  = tid >> 1;
        int d0 = (tid & 1) * 16;
        uint4 x0 = qg[u], x1 = qg[u + 1];
        *reinterpret_cast<uint4*>(&qs[p * APH + d0])     = x0;
        *reinterpret_cast<uint4*>(&qs[p * APH + d0 + 8]) = x1;
        uint4 y0 = kg[u], y1 = kg[u + 1];
        *reinterpret_cast<uint4*>(&ks[p * APH + d0])     = y0;
        *reinterpret_cast<uint4*>(&ks[p * APH + d0 + 8]) = y1;
        uint4 z0 = vg[u], z1 = vg[u + 1];
        *reinterpret_cast<uint4*>(&vs[p * APH + d0])     = z0;
        *reinterpret_cast<uint4*>(&vs[p * APH + d0 + 8]) = z1;
    }
    __syncthreads();

    const int w    = tid >> 5;
    const int lane = tid & 31;
    const int g    = lane >> 2;
    const int t4   = lane & 3;
    const int r0   = w * 16;
    const int lrow = lane & 7;

    // Phase1 ldmatrix addresses
    uint32_t qAddr = sm_a(&qs[(r0 + lrow + ((lane >> 3) & 1) * 8) * APH + ((lane >> 4) & 1) * 8]);
    uint32_t kAddr = sm_a(&ks[(lrow + ((lane >> 4) & 1) * 8) * APH + ((lane >> 3) & 1) * 8]);
    // Phase2 (trans): tiles 0:(kb,n0) 1:(kb+8,n0) 2:(kb,n0+8) 3:(kb+8,n0+8)
    uint32_t vAddr = sm_a(&vs[(lrow + ((lane >> 3) & 1) * 8) * APH + ((lane >> 4) & 1) * 8]);

    // Phase 1: sim = q @ k^T  (M=16/warp, N=64, K=32)
    float c1[8][4];
#pragma unroll
    for (int nj = 0; nj < 8; nj++)
#pragma unroll
        for (int k = 0; k < 4; k++) c1[nj][k] = 0.f;

#pragma unroll
    for (int k16 = 0; k16 < 2; ++k16) {
        uint32_t a0, a1, a2, a3;
        ldsm4(a0, a1, a2, a3, qAddr + k16 * 32);
#pragma unroll
        for (int jp = 0; jp < 4; ++jp) {
            uint32_t b00, b10, b01, b11;
            ldsm4(b00, b10, b01, b11, kAddr + jp * (16 * APH * 2) + k16 * 32);
            mma_f16(c1[2*jp],   a0, a1, a2, a3, b00, b10);
            mma_f16(c1[2*jp+1], a0, a1, a2, a3, b01, b11);
        }
    }

    // scale + bias + mask in registers
    const size_t bbias = ((size_t)s * NH + head) * 4096;
    const bool mh = ((win >> 5) == 31);
    const bool mw = ((win & 31) == 31);
    const float scale = 0.17677669529663687f;
    const int rowA = r0 + g, rowB = rowA + 8;
    const int ipA = rowA >> 3, jpA = rowA & 7;
    const int ipB = rowB >> 3, jpB = rowB & 7;
    const int jq0 = 2 * t4, jq1 = 2 * t4 + 1;
    const bool wj0 = mw && ((jq0 < 4) != 0), wj1 = mw && ((jq1 < 4) != 0);
    (void)wj0; (void)wj1;

    float mA = -1e30f, mB = -1e30f;
#pragma unroll
    for (int nj = 0; nj < 8; nj++) {
        int col = nj * 8 + 2 * t4;
        int iq  = col >> 3;
        float2 bA = *reinterpret_cast<const float2*>(&g_bias[bbias + rowA * 64 + col]);
        float2 bB = *reinterpret_cast<const float2*>(&g_bias[bbias + rowB * 64 + col]);
        bool hA = mh && ((ipA < 4) != (iq < 4));
        bool hB = mh && ((ipB < 4) != (iq < 4));
        bool w0A = hA || (mw && ((jpA < 4) != (jq0 < 4)));
        bool w1A = hA || (mw && ((jpA < 4) != (jq1 < 4)));
        bool w0B = hB || (mw && ((jpB < 4) != (jq0 < 4)));
        bool w1B = hB || (mw && ((jpB < 4) != (jq1 < 4)));
        float v0 = w0A ? -1e30f : c1[nj][0] * scale + bA.x;
        float v1 = w1A ? -1e30f : c1[nj][1] * scale + bA.y;
        float v2 = w0B ? -1e30f : c1[nj][2] * scale + bB.x;
        float v3 = w1B ? -1e30f : c1[nj][3] * scale + bB.y;
        c1[nj][0] = v0; c1[nj][1] = v1; c1[nj][2] = v2; c1[nj][3] = v3;
        mA = fmaxf(mA, fmaxf(v0, v1));
        mB = fmaxf(mB, fmaxf(v2, v3));
    }
    mA = fmaxf(mA, __shfl_xor_sync(0xffffffffu, mA, 1));
    mA = fmaxf(mA, __shfl_xor_sync(0xffffffffu, mA, 2));
    mB = fmaxf(mB, __shfl_xor_sync(0xffffffffu, mB, 1));
    mB = fmaxf(mB, __shfl_xor_sync(0xffffffffu, mB, 2));

    float sA = 0.f, sB = 0.f;
#pragma unroll
    for (int nj = 0; nj < 8; nj++) {
        float e0 = __expf(c1[nj][0] - mA);
        float e1 = __expf(c1[nj][1] - mA);
        float e2 = __expf(c1[nj][2] - mB);
        float e3 = __expf(c1[nj][3] - mB);
        c1[nj][0] = e0; c1[nj][1] = e1; c1[nj][2] = e2; c1[nj][3] = e3;
        sA += e0 + e1; sB += e2 + e3;
    }
    sA += __shfl_xor_sync(0xffffffffu, sA, 1);
    sA += __shfl_xor_sync(0xffffffffu, sA, 2);
    sB += __shfl_xor_sync(0xffffffffu, sB, 1);
    sB += __shfl_xor_sync(0xffffffffu, sB, 2);
    const float invA = 1.f / sA, invB = 1.f / sB;

    // Phase 2: o = P @ V  (P fragments come straight from c1 registers)
    float c2[4][4];
#pragma unroll
    for (int nj = 0; nj < 4; nj++)
#pragma unroll
        for (int k = 0; k < 4; k++) c2[nj][k] = 0.f;

#pragma unroll
    for (int k16 = 0; k16 < 4; ++k16) {
        uint32_t a0 = f22u(c1[2*k16][0]   * invA, c1[2*k16][1]   * invA);
        uint32_t a1 = f22u(c1[2*k16][2]   * invB, c1[2*k16][3]   * invB);
        uint32_t a2 = f22u(c1[2*k16+1][0] * invA, c1[2*k16+1][1] * invA);
        uint32_t a3 = f22u(c1[2*k16+1][2] * invB, c1[2*k16+1][3] * invB);
#pragma unroll
        for (int jp = 0; jp < 2; ++jp) {
            uint32_t b00, b10, b01, b11;
            ldsm4t(b00, b10, b01, b11, vAddr + k16 * (16 * APH * 2) + jp * 32);
            mma_f16(c2[2*jp],   a0, a1, a2, a3, b00, b10);
            mma_f16(c2[2*jp+1], a0, a1, a2, a3, b01, b11);
        }
    }

    // Write o (fp16) to g_attnh [s][b][win][p][head*32 + d]
    const size_t obase = (size_t)s * ((size_t)BB * NWIN * PP * CC)
                       + (((size_t)b * NWIN + win) * PP) * CC
                       + (size_t)head * HD;
#pragma unroll
    for (int nj = 0; nj < 4; nj++) {
#pragma unroll
        for (int h2 = 0; h2 < 2; h2++) {
            int row = r0 + g + 8 * h2;
            int col = nj * 8 + t4 * 2;
            __half2 hv = __floats2half2_rn(c2[nj][h2 * 2 + 0], c2[nj][h2 * 2 + 1]);
            *reinterpret_cast<__half2*>(&g_attnh[obase + (size_t)row * CC + col]) = hv;
        }
    }
}

// ---------------------------------------------------------------------------
// Kernel 3: output projection (fp16 mma + ldmatrix) + unwindow + roll scatter.
// ---------------------------------------------------------------------------
__global__ __launch_bounds__(256)
void proj_mma(const float* __restrict__ bo1, const float* __restrict__ bo2,
              float* __restrict__ out)
{
    __shared__ __align__(16) __half As[128 * APH];
    __shared__ __align__(16) __half Bs[128 * APH];

    const int s = blockIdx.z;
    const float* __restrict__ bo = s ? bo2 : bo1;
    float* __restrict__ dst = out + (size_t)s * ((size_t)BB * HH * WW * OUTC);
    const int colBlock = blockIdx.x;     // 0..1
    const int rowBlock = blockIdx.y;     // 0..1023
    const int tid  = threadIdx.x;
    const int wid  = tid >> 5;
    const int lane = tid & 31;
    const int g    = lane >> 2;
    const int t4   = lane & 3;
    const int lrow = lane & 7;

    const int arow  = tid >> 1;
    const int apart = tid & 1;
    const int acol  = apart * 16;
    const uint4* aR = reinterpret_cast<const uint4*>(
        g_attnh + (size_t)s * ((size_t)BB * NWIN * PP * CC)
                + (size_t)(rowBlock * 128 + arow) * CC);

    const uint4* wb4 = reinterpret_cast<const uint4*>(
        g_wh + 393216 + (size_t)(s * 2 + colBlock) * 32768);
    const int bidx0 = (tid >> 1) * 4 + apart * 2;

    const int wrb = (wid & 3) * 32;
    const int wcb = (wid >> 2) * 64;

    uint32_t aAddr0 = sm_a(&As[(wrb +      lrow + ((lane >> 3) & 1) * 8) * APH + ((lane >> 4) & 1) * 8]);
    uint32_t aAddr1 = sm_a(&As[(wrb + 16 + lrow + ((lane >> 3) & 1) * 8) * APH + ((lane >> 4) & 1) * 8]);
    uint32_t bAddr  = sm_a(&Bs[(wcb + lrow + ((lane >> 4) & 1) * 8) * APH + ((lane >> 3) & 1) * 8]);

    float acc[2][8][4];
#pragma unroll
    for (int mi = 0; mi < 2; mi++)
#pragma unroll
        for (int nj = 0; nj < 8; nj++)
#pragma unroll
            for (int k = 0; k < 4; k++) acc[mi][nj][k] = 0.f;

    uint4 aPre[2], bPre[2];
    aPre[0] = aR[apart * 2];     aPre[1] = aR[apart * 2 + 1];
    bPre[0] = wb4[bidx0];        bPre[1] = wb4[bidx0 + 1];

    for (int c = 0; c < 8; ++c) {
        *reinterpret_cast<uint4*>(&As[arow * APH + acol])     = aPre[0];
        *reinterpret_cast<uint4*>(&As[arow * APH + acol + 8]) = aPre[1];
        *reinterpret_cast<uint4*>(&Bs[(tid >> 1) * APH + acol])     = bPre[0];
        *reinterpret_cast<uint4*>(&Bs[(tid >> 1) * APH + acol + 8]) = bPre[1];
        __syncthreads();
        if (c < 7) {
            aPre[0] = aR[(c + 1) * 4 + apart * 2];
            aPre[1] = aR[(c + 1) * 4 + apart * 2 + 1];
            bPre[0] = wb4[(c + 1) * 512 + bidx0];
            bPre[1] = wb4[(c + 1) * 512 + bidx0 + 1];
        }
#pragma unroll
        for (int k16 = 0; k16 < 2; ++k16) {
            uint32_t a0[2], a1[2], a2[2], a3[2];
            ldsm4(a0[0], a1[0], a2[0], a3[0], aAddr0 + k16 * 32);
            ldsm4(a0[1], a1[1], a2[1], a3[1], aAddr1 + k16 * 32);
#pragma unroll
            for (int jp = 0; jp < 4; ++jp) {
                uint32_t b00, b10, b01, b11;
                ldsm4(b00, b10, b01, b11, bAddr + jp * (16 * APH * 2) + k16 * 32);
                mma_f16(acc[0][2*jp],   a0[0], a1[0], a2[0], a3[0], b00, b10);
                mma_f16(acc[0][2*jp+1], a0[0], a1[0], a2[0], a3[0], b01, b11);
                mma_f16(acc[1][2*jp],   a0[1], a1[1], a2[1], a3[1], b00, b10);
                mma_f16(acc[1][2*jp+1], a0[1], a1[1], a2[1], a3[1], b01, b11);
            }
        }
        __syncthreads();
    }

    // Epilogue: unwindow + roll scatter (fp32 output)
#pragma unroll
    for (int mi = 0; mi < 2; mi++) {
#pragma unroll
        for (int h = 0; h < 2; h++) {
            int r  = rowBlock * 128 + wrb + mi * 16 + g + 8 * h;
            int pr = r & 63, wr = (r >> 6) & 1023, br = r >> 16;
            int hout = (((wr >> 5) << 3) + (pr >> 3) + SHIFT) & 255;
            int wout = ((wr & 31) << 3) + (pr & 7);
            size_t rowbase = (((size_t)br * HH + hout) * WW + wout) * OUTC;
#pragma unroll
            for (int nj = 0; nj < 8; nj++) {
                int n = colBlock * 128 + wcb + nj * 8 + t4 * 2;
                float2 v;
                v.x = acc[mi][nj][h * 2 + 0] + bo[n];
                v.y = acc[mi][nj][h * 2 + 1] + bo[n + 1];
                *reinterpret_cast<float2*>(&dst[rowbase + n]) = v;
            }
        }
    }
}

// ---------------------------------------------------------------------------
// Launch
// ---------------------------------------------------------------------------
extern "C" void kernel_launch(void* const* d_in, const int* in_sizes, int n_in,
                              void* d_out, int out_size)
{
    const float* emb1  = (const float*)d_in[0];
    const float* emb2  = (const float*)d_in[1];
    const float* Wqkv1 = (const float*)d_in[2];
    const float* bqkv1 = (const float*)d_in[3];
    const float* Wqkv2 = (const float*)d_in[4];
    const float* bqkv2 = (const float*)d_in[5];
    const float* rel1  = (const float*)d_in[6];
    const float* rel2  = (const float*)d_in[7];
    const float* Wo1   = (const float*)d_in[8];
    const float* bo1   = (const float*)d_in[9];
    const float* Wo2   = (const float*)d_in[10];
    const float* bo2   = (const float*)d_in[11];
    float* out = (float*)d_out;
    (void)in_sizes; (void)n_in; (void)out_size;

    bias_kernel<<<256, 256>>>(rel1, rel2);
    wpack_kernel<<<2048, 256>>>(Wqkv1, Wqkv2, Wo1, Wo2);

    dim3 gq(6, 1024, 2);
    qkv_mma<<<gq, 256>>>(emb1, emb2, bqkv1, bqkv2);

    dim3 ga(2048, 8, 2);
    attn_mma<<<ga, 128>>>();

    dim3 gp(2, 1024, 2);
    proj_mma<<<gp, 256>>>(bo1, bo2, out);
}

// round 12
// speedup vs baseline: 5.4207x; 1.7664x over previous
#include <cuda_runtime.h>
#include <cuda_fp16.h>
#include <cstdint>

// Problem constants
#define BB 2
#define HH 256
#define WW 256
#define CC 256
#define WS 8
#define SHIFT 4
#define NH 8
#define HD 32
#define OUTC 256
#define NWIN 1024
#define PP 64
#define MROWS 131072

// Scratch (device globals)
__device__ __half g_embh[2u*131072u*256u];          // rolled+windowed emb, fp16 [s][R][k]
__device__ __half g_qkvh[2u*3u*BB*NWIN*NH*PP*HD];   // [s][qkv][b][win][head][p][d] fp16
__device__ __half g_attnh[2u*BB*NWIN*PP*CC];        // [s][b][win][p][C] fp16
__device__ float  g_bias[2*NH*PP*PP];
__device__ __half g_wh[524288];                     // packed fp16 weights [n][k]

__device__ __forceinline__ uint32_t f22u(float a, float b) {
    __half2 h = __floats2half2_rn(a, b);
    return *reinterpret_cast<uint32_t*>(&h);
}

__device__ __forceinline__ void mma_f16(float c[4],
                                        uint32_t a0, uint32_t a1, uint32_t a2, uint32_t a3,
                                        uint32_t b0, uint32_t b1) {
    asm volatile(
        "mma.sync.aligned.m16n8k16.row.col.f32.f16.f16.f32 "
        "{%0,%1,%2,%3}, {%4,%5,%6,%7}, {%8,%9}, {%0,%1,%2,%3};"
        : "+f"(c[0]), "+f"(c[1]), "+f"(c[2]), "+f"(c[3])
        : "r"(a0), "r"(a1), "r"(a2), "r"(a3), "r"(b0), "r"(b1));
}

__device__ __forceinline__ void ldsm4(uint32_t& r0, uint32_t& r1, uint32_t& r2, uint32_t& r3,
                                      uint32_t addr) {
    asm volatile("ldmatrix.sync.aligned.m8n8.x4.shared.b16 {%0,%1,%2,%3}, [%4];"
                 : "=r"(r0), "=r"(r1), "=r"(r2), "=r"(r3) : "r"(addr));
}
__device__ __forceinline__ void ldsm4t(uint32_t& r0, uint32_t& r1, uint32_t& r2, uint32_t& r3,
                                       uint32_t addr) {
    asm volatile("ldmatrix.sync.aligned.m8n8.x4.trans.shared.b16 {%0,%1,%2,%3}, [%4];"
                 : "=r"(r0), "=r"(r1), "=r"(r2), "=r"(r3) : "r"(addr));
}
__device__ __forceinline__ uint32_t sm_a(const void* p) {
    return (uint32_t)__cvta_generic_to_shared(p);
}
__device__ __forceinline__ void cpa16(uint32_t saddr, const void* g) {
    asm volatile("cp.async.cg.shared.global [%0], [%1], 16;"
                 :: "r"(saddr), "l"(g));
}
#define CP_COMMIT() asm volatile("cp.async.commit_group;")

#define APH 40                 // half pitch; row stride 80B -> conflict-free ldmatrix
#define STAGE_BYTES 20480      // (A 128x40 + B 128x40) halves per stage
#define GEMM_SMEM  (3 * STAGE_BYTES)

// ---------------------------------------------------------------------------
// Kernel 0a: bias table
// ---------------------------------------------------------------------------
__global__ void bias_kernel(const float* __restrict__ rel1,
                            const float* __restrict__ rel2)
{
    int idx = blockIdx.x * blockDim.x + threadIdx.x;
    int s = idx >> 15, head = (idx >> 12) & 7, p = (idx >> 6) & 63, q = idx & 63;
    const float* rel = s ? rel2 : rel1;
    int a = (p >> 3) - (q >> 3) + 7;
    int b = (p & 7) - (q & 7) + 7;
    g_bias[idx] = rel[head * 225 + a * 15 + b];
}

// ---------------------------------------------------------------------------
// Kernel 0b: pack weights into fp16 [kc][n][k] layout per (s,cb)
// ---------------------------------------------------------------------------
__global__ void wpack_kernel(const float* __restrict__ Wqkv1,
                             const float* __restrict__ Wqkv2,
                             const float* __restrict__ Wo1,
                             const float* __restrict__ Wo2)
{
    int idx = blockIdx.x * blockDim.x + threadIdx.x;   // 0..524287
    const float* W;
    int N, cb, r;
    if (idx < 393216) {
        int scb = idx >> 15;
        r = idx & 32767;
        int s = scb / 6; cb = scb % 6;
        W = s ? Wqkv2 : Wqkv1; N = 768;
    } else {
        int t = idx - 393216;
        int scb = t >> 15;
        r = t & 32767;
        int s = scb >> 1; cb = scb & 1;
        W = s ? Wo2 : Wo1; N = 256;
    }
    int kc = r >> 12;
    int r2 = r & 4095;
    int nl = r2 >> 5, kk = r2 & 31;
    int k = kc * 32 + kk;
    int n = cb * 128 + nl;
    g_wh[idx] = __float2half_rn(W[k * N + n]);
}

// ---------------------------------------------------------------------------
// Kernel 0c: emb -> fp16 with fused roll + window gather ([s][R][k] rows)
// ---------------------------------------------------------------------------
__global__ __launch_bounds__(256)
void embh_kernel(const float* __restrict__ emb1, const float* __restrict__ emb2)
{
    unsigned idx = blockIdx.x * 256 + threadIdx.x;   // 0..8388607, 8 halves each
    int s = idx >> 22;
    unsigned r = idx & 4194303u;
    unsigned R = r >> 5, gi = r & 31;
    int p_ = R & 63, win_ = (R >> 6) & 1023, b_ = R >> 16;
    int hs = (((win_ >> 5) << 3) + (p_ >> 3) + SHIFT) & 255;
    int ws = ((win_ & 31) << 3) + (p_ & 7);
    const float* src = (s ? emb2 : emb1)
                     + ((((size_t)b_ * HH + hs) * WW + ws) * CC) + gi * 8;
    float4 f0 = *reinterpret_cast<const float4*>(src);
    float4 f1 = *reinterpret_cast<const float4*>(src + 4);
    uint4 o;
    o.x = f22u(f0.x, f0.y); o.y = f22u(f0.z, f0.w);
    o.z = f22u(f1.x, f1.y); o.w = f22u(f1.z, f1.w);
    *reinterpret_cast<uint4*>(&g_embh[((size_t)s << 25) + (size_t)R * 256 + gi * 8]) = o;
}

// ---------------------------------------------------------------------------
// Kernel 1: QKV GEMM (fp16 mma + ldmatrix + cp.async 3-stage pipeline).
// ---------------------------------------------------------------------------
__global__ __launch_bounds__(256)
void qkv_mma(const float* __restrict__ bqkv1, const float* __restrict__ bqkv2)
{
    extern __shared__ __align__(16) __half sh[];
    const int s = blockIdx.z;
    const float* __restrict__ bq = s ? bqkv2 : bqkv1;
    const int colBlock = blockIdx.x;     // 0..5
    const int rowBlock = blockIdx.y;     // 0..1023
    const int tid  = threadIdx.x;
    const int wid  = tid >> 5;
    const int lane = tid & 31;
    const int g    = lane >> 2;
    const int t4   = lane & 3;
    const int lrow = lane & 7;

    const __half* aBase = g_embh + ((size_t)s << 25) + (size_t)rowBlock * 128 * 256;
    const __half* bBase = g_wh + (size_t)(s * 6 + colBlock) * 32768;

    const uint32_t smemBase = sm_a(sh);
    // cp.async unit mapping: 512 16B-units per matrix per chunk, 2 per thread
    const int ra0 = tid >> 2,        ca0 = tid & 3;
    const int ra1 = (tid + 256) >> 2, ca1 = tid & 3;   // (tid+256)&3 == tid&3

    const int wrb = (wid & 3) * 32;
    const int wcb = (wid >> 2) * 64;
    const uint32_t aOff0 = ((wrb + lrow + ((lane >> 3) & 1) * 8) * APH + ((lane >> 4) & 1) * 8) * 2;
    const uint32_t aOff1 = aOff0 + 16 * APH * 2;
    const uint32_t bOff  = ((wcb + lrow + ((lane >> 4) & 1) * 8) * APH + ((lane >> 3) & 1) * 8) * 2
                         + 10240;

#define QISSUE(c, st) do {                                                        \
    uint32_t ab = smemBase + (st) * STAGE_BYTES;                                  \
    uint32_t bb = ab + 10240;                                                     \
    cpa16(ab + ra0 * 80 + ca0 * 16, aBase + (size_t)ra0 * 256 + (c) * 32 + ca0 * 8); \
    cpa16(ab + ra1 * 80 + ca1 * 16, aBase + (size_t)ra1 * 256 + (c) * 32 + ca1 * 8); \
    cpa16(bb + ra0 * 80 + ca0 * 16, bBase + (size_t)(c) * 4096 + ra0 * 32 + ca0 * 8); \
    cpa16(bb + ra1 * 80 + ca1 * 16, bBase + (size_t)(c) * 4096 + ra1 * 32 + ca1 * 8); \
    CP_COMMIT();                                                                  \
} while (0)

    float acc[2][8][4];
#pragma unroll
    for (int mi = 0; mi < 2; mi++)
#pragma unroll
        for (int nj = 0; nj < 8; nj++)
#pragma unroll
            for (int k = 0; k < 4; k++) acc[mi][nj][k] = 0.f;

    QISSUE(0, 0);
    QISSUE(1, 1);

#pragma unroll
    for (int c = 0; c < 8; ++c) {
        const int st = c % 3;
        if (c < 7) asm volatile("cp.async.wait_group 1;");
        else       asm volatile("cp.async.wait_group 0;");
        __syncthreads();
        if (c < 6) QISSUE(c + 2, (c + 2) % 3);

        const uint32_t stb = smemBase + st * STAGE_BYTES;
#pragma unroll
        for (int k16 = 0; k16 < 2; ++k16) {
            uint32_t a0[2], a1[2], a2[2], a3[2];
            ldsm4(a0[0], a1[0], a2[0], a3[0], stb + aOff0 + k16 * 32);
            ldsm4(a0[1], a1[1], a2[1], a3[1], stb + aOff1 + k16 * 32);
#pragma unroll
            for (int jp = 0; jp < 4; ++jp) {
                uint32_t b00, b10, b01, b11;
                ldsm4(b00, b10, b01, b11, stb + bOff + jp * 1280 + k16 * 32);
                mma_f16(acc[0][2*jp],   a0[0], a1[0], a2[0], a3[0], b00, b10);
                mma_f16(acc[0][2*jp+1], a0[0], a1[0], a2[0], a3[0], b01, b11);
                mma_f16(acc[1][2*jp],   a0[1], a1[1], a2[1], a3[1], b00, b10);
                mma_f16(acc[1][2*jp+1], a0[1], a1[1], a2[1], a3[1], b01, b11);
            }
        }
    }
#undef QISSUE

    // Epilogue: add bias, convert fp16, scatter to q/k/v layout
#pragma unroll
    for (int mi = 0; mi < 2; mi++) {
#pragma unroll
        for (int h = 0; h < 2; h++) {
            int r  = rowBlock * 128 + wrb + mi * 16 + g + 8 * h;
            int pr = r & 63, wr = (r >> 6) & 1023, br = r >> 16;
#pragma unroll
            for (int nj = 0; nj < 8; nj++) {
                int n = colBlock * 128 + wcb + nj * 8 + t4 * 2;
                float vx = acc[mi][nj][h * 2 + 0] + bq[n];
                float vy = acc[mi][nj][h * 2 + 1] + bq[n + 1];
                int qkvi = n >> 8, head = (n >> 5) & 7, d = n & 31;
                size_t idx = ((((size_t)(s * 3 + qkvi) * BB + br) * NWIN + wr) * NH + head)
                                 * ((size_t)PP * HD)
                             + (size_t)pr * HD + d;
                __half2 hv = __floats2half2_rn(vx, vy);
                *reinterpret_cast<__half2*>(&g_qkvh[idx]) = hv;
            }
        }
    }
}

// ---------------------------------------------------------------------------
// Kernel 2: windowed cross-attention, register softmax + ldmatrix (unchanged).
// ---------------------------------------------------------------------------
__global__ __launch_bounds__(128)
void attn_mma()
{
    const int s    = blockIdx.z;
    const int head = blockIdx.y;
    const int bw   = blockIdx.x;
    const int b    = bw >> 10;
    const int win  = bw & 1023;
    const int os   = 1 - s;

    __shared__ __align__(16) __half qs[64 * APH];
    __shared__ __align__(16) __half ks[64 * APH];
    __shared__ __align__(16) __half vs[64 * APH];   // [p][d]

    const int tid = threadIdx.x;
    const size_t tile = (size_t)PP * HD;
    const size_t qbase = (((((size_t)s  * 3 + 0) * BB + b) * NWIN + win) * NH + head) * tile;
    const size_t kbase = (((((size_t)os * 3 + 1) * BB + b) * NWIN + win) * NH + head) * tile;
    const size_t vbase = (((((size_t)os * 3 + 2) * BB + b) * NWIN + win) * NH + head) * tile;

    {
        const uint4* qg = reinterpret_cast<const uint4*>(&g_qkvh[qbase]);
        const uint4* kg = reinterpret_cast<const uint4*>(&g_qkvh[kbase]);
        const uint4* vg = reinterpret_cast<const uint4*>(&g_qkvh[vbase]);
        int u  = tid * 2;
        int p  = tid >> 1;
        int d0 = (tid & 1) * 16;
        uint4 x0 = qg[u], x1 = qg[u + 1];
        *reinterpret_cast<uint4*>(&qs[p * APH + d0])     = x0;
        *reinterpret_cast<uint4*>(&qs[p * APH + d0 + 8]) = x1;
        uint4 y0 = kg[u], y1 = kg[u + 1];
        *reinterpret_cast<uint4*>(&ks[p * APH + d0])     = y0;
        *reinterpret_cast<uint4*>(&ks[p * APH + d0 + 8]) = y1;
        uint4 z0 = vg[u], z1 = vg[u + 1];
        *reinterpret_cast<uint4*>(&vs[p * APH + d0])     = z0;
        *reinterpret_cast<uint4*>(&vs[p * APH + d0 + 8]) = z1;
    }
    __syncthreads();

    const int w    = tid >> 5;
    const int lane = tid & 31;
    const int g    = lane >> 2;
    const int t4   = lane & 3;
    const int r0   = w * 16;
    const int lrow = lane & 7;

    uint32_t qAddr = sm_a(&qs[(r0 + lrow + ((lane >> 3) & 1) * 8) * APH + ((lane >> 4) & 1) * 8]);
    uint32_t kAddr = sm_a(&ks[(lrow + ((lane >> 4) & 1) * 8) * APH + ((lane >> 3) & 1) * 8]);
    uint32_t vAddr = sm_a(&vs[(lrow + ((lane >> 3) & 1) * 8) * APH + ((lane >> 4) & 1) * 8]);

    float c1[8][4];
#pragma unroll
    for (int nj = 0; nj < 8; nj++)
#pragma unroll
        for (int k = 0; k < 4; k++) c1[nj][k] = 0.f;

#pragma unroll
    for (int k16 = 0; k16 < 2; ++k16) {
        uint32_t a0, a1, a2, a3;
        ldsm4(a0, a1, a2, a3, qAddr + k16 * 32);
#pragma unroll
        for (int jp = 0; jp < 4; ++jp) {
            uint32_t b00, b10, b01, b11;
            ldsm4(b00, b10, b01, b11, kAddr + jp * (16 * APH * 2) + k16 * 32);
            mma_f16(c1[2*jp],   a0, a1, a2, a3, b00, b10);
            mma_f16(c1[2*jp+1], a0, a1, a2, a3, b01, b11);
        }
    }

    const size_t bbias = ((size_t)s * NH + head) * 4096;
    const bool mh = ((win >> 5) == 31);
    const bool mw = ((win & 31) == 31);
    const float scale = 0.17677669529663687f;
    const int rowA = r0 + g, rowB = rowA + 8;
    const int ipA = rowA >> 3, jpA = rowA & 7;
    const int ipB = rowB >> 3, jpB = rowB & 7;
    const int jq0 = 2 * t4, jq1 = 2 * t4 + 1;

    float mA = -1e30f, mB = -1e30f;
#pragma unroll
    for (int nj = 0; nj < 8; nj++) {
        int col = nj * 8 + 2 * t4;
        int iq  = col >> 3;
        float2 bA = *reinterpret_cast<const float2*>(&g_bias[bbias + rowA * 64 + col]);
        float2 bB = *reinterpret_cast<const float2*>(&g_bias[bbias + rowB * 64 + col]);
        bool hA = mh && ((ipA < 4) != (iq < 4));
        bool hB = mh && ((ipB < 4) != (iq < 4));
        bool w0A = hA || (mw && ((jpA < 4) != (jq0 < 4)));
        bool w1A = hA || (mw && ((jpA < 4) != (jq1 < 4)));
        bool w0B = hB || (mw && ((jpB < 4) != (jq0 < 4)));
        bool w1B = hB || (mw && ((jpB < 4) != (jq1 < 4)));
        float v0 = w0A ? -1e30f : c1[nj][0] * scale + bA.x;
        float v1 = w1A ? -1e30f : c1[nj][1] * scale + bA.y;
        float v2 = w0B ? -1e30f : c1[nj][2] * scale + bB.x;
        float v3 = w1B ? -1e30f : c1[nj][3] * scale + bB.y;
        c1[nj][0] = v0; c1[nj][1] = v1; c1[nj][2] = v2; c1[nj][3] = v3;
        mA = fmaxf(mA, fmaxf(v0, v1));
        mB = fmaxf(mB, fmaxf(v2, v3));
    }
    mA = fmaxf(mA, __shfl_xor_sync(0xffffffffu, mA, 1));
    mA = fmaxf(mA, __shfl_xor_sync(0xffffffffu, mA, 2));
    mB = fmaxf(mB, __shfl_xor_sync(0xffffffffu, mB, 1));
    mB = fmaxf(mB, __shfl_xor_sync(0xffffffffu, mB, 2));

    float sA = 0.f, sB = 0.f;
#pragma unroll
    for (int nj = 0; nj < 8; nj++) {
        float e0 = __expf(c1[nj][0] - mA);
        float e1 = __expf(c1[nj][1] - mA);
        float e2 = __expf(c1[nj][2] - mB);
        float e3 = __expf(c1[nj][3] - mB);
        c1[nj][0] = e0; c1[nj][1] = e1; c1[nj][2] = e2; c1[nj][3] = e3;
        sA += e0 + e1; sB += e2 + e3;
    }
    sA += __shfl_xor_sync(0xffffffffu, sA, 1);
    sA += __shfl_xor_sync(0xffffffffu, sA, 2);
    sB += __shfl_xor_sync(0xffffffffu, sB, 1);
    sB += __shfl_xor_sync(0xffffffffu, sB, 2);
    const float invA = 1.f / sA, invB = 1.f / sB;

    float c2[4][4];
#pragma unroll
    for (int nj = 0; nj < 4; nj++)
#pragma unroll
        for (int k = 0; k < 4; k++) c2[nj][k] = 0.f;

#pragma unroll
    for (int k16 = 0; k16 < 4; ++k16) {
        uint32_t a0 = f22u(c1[2*k16][0]   * invA, c1[2*k16][1]   * invA);
        uint32_t a1 = f22u(c1[2*k16][2]   * invB, c1[2*k16][3]   * invB);
        uint32_t a2 = f22u(c1[2*k16+1][0] * invA, c1[2*k16+1][1] * invA);
        uint32_t a3 = f22u(c1[2*k16+1][2] * invB, c1[2*k16+1][3] * invB);
#pragma unroll
        for (int jp = 0; jp < 2; ++jp) {
            uint32_t b00, b10, b01, b11;
            ldsm4t(b00, b10, b01, b11, vAddr + k16 * (16 * APH * 2) + jp * 32);
            mma_f16(c2[2*jp],   a0, a1, a2, a3, b00, b10);
            mma_f16(c2[2*jp+1], a0, a1, a2, a3, b01, b11);
        }
    }

    const size_t obase = (size_t)s * ((size_t)BB * NWIN * PP * CC)
                       + (((size_t)b * NWIN + win) * PP) * CC
                       + (size_t)head * HD;
#pragma unroll
    for (int nj = 0; nj < 4; nj++) {
#pragma unroll
        for (int h2 = 0; h2 < 2; h2++) {
            int row = r0 + g + 8 * h2;
            int col = nj * 8 + t4 * 2;
            __half2 hv = __floats2half2_rn(c2[nj][h2 * 2 + 0], c2[nj][h2 * 2 + 1]);
            *reinterpret_cast<__half2*>(&g_attnh[obase + (size_t)row * CC + col]) = hv;
        }
    }
}

// ---------------------------------------------------------------------------
// Kernel 3: output projection (fp16 mma + ldmatrix + cp.async pipeline).
// ---------------------------------------------------------------------------
__global__ __launch_bounds__(256)
void proj_mma(const float* __restrict__ bo1, const float* __restrict__ bo2,
              float* __restrict__ out)
{
    extern __shared__ __align__(16) __half sh[];
    const int s = blockIdx.z;
    const float* __restrict__ bo = s ? bo2 : bo1;
    float* __restrict__ dst = out + (size_t)s * ((size_t)BB * HH * WW * OUTC);
    const int colBlock = blockIdx.x;     // 0..1
    const int rowBlock = blockIdx.y;     // 0..1023
    const int tid  = threadIdx.x;
    const int wid  = tid >> 5;
    const int lane = tid & 31;
    const int g    = lane >> 2;
    const int t4   = lane & 3;
    const int lrow = lane & 7;

    const __half* aBase = g_attnh + (size_t)s * ((size_t)BB * NWIN * PP * CC)
                        + (size_t)rowBlock * 128 * 256;
    const __half* bBase = g_wh + 393216 + (size_t)(s * 2 + colBlock) * 32768;

    const uint32_t smemBase = sm_a(sh);
    const int ra0 = tid >> 2,         ca0 = tid & 3;
    const int ra1 = (tid + 256) >> 2, ca1 = tid & 3;

    const int wrb = (wid & 3) * 32;
    const int wcb = (wid >> 2) * 64;
    const uint32_t aOff0 = ((wrb + lrow + ((lane >> 3) & 1) * 8) * APH + ((lane >> 4) & 1) * 8) * 2;
    const uint32_t aOff1 = aOff0 + 16 * APH * 2;
    const uint32_t bOff  = ((wcb + lrow + ((lane >> 4) & 1) * 8) * APH + ((lane >> 3) & 1) * 8) * 2
                         + 10240;

#define PISSUE(c, st) do {                                                        \
    uint32_t ab = smemBase + (st) * STAGE_BYTES;                                  \
    uint32_t bb = ab + 10240;                                                     \
    cpa16(ab + ra0 * 80 + ca0 * 16, aBase + (size_t)ra0 * 256 + (c) * 32 + ca0 * 8); \
    cpa16(ab + ra1 * 80 + ca1 * 16, aBase + (size_t)ra1 * 256 + (c) * 32 + ca1 * 8); \
    cpa16(bb + ra0 * 80 + ca0 * 16, bBase + (size_t)(c) * 4096 + ra0 * 32 + ca0 * 8); \
    cpa16(bb + ra1 * 80 + ca1 * 16, bBase + (size_t)(c) * 4096 + ra1 * 32 + ca1 * 8); \
    CP_COMMIT();                                                                  \
} while (0)

    float acc[2][8][4];
#pragma unroll
    for (int mi = 0; mi < 2; mi++)
#pragma unroll
        for (int nj = 0; nj < 8; nj++)
#pragma unroll
            for (int k = 0; k < 4; k++) acc[mi][nj][k] = 0.f;

    PISSUE(0, 0);
    PISSUE(1, 1);

#pragma unroll
    for (int c = 0; c < 8; ++c) {
        const int st = c % 3;
        if (c < 7) asm volatile("cp.async.wait_group 1;");
        else       asm volatile("cp.async.wait_group 0;");
        __syncthreads();
        if (c < 6) PISSUE(c + 2, (c + 2) % 3);

        const uint32_t stb = smemBase + st * STAGE_BYTES;
#pragma unroll
        for (int k16 = 0; k16 < 2; ++k16) {
            uint32_t a0[2], a1[2], a2[2], a3[2];
            ldsm4(a0[0], a1[0], a2[0], a3[0], stb + aOff0 + k16 * 32);
            ldsm4(a0[1], a1[1], a2[1], a3[1], stb + aOff1 + k16 * 32);
#pragma unroll
            for (int jp = 0; jp < 4; ++jp) {
                uint32_t b00, b10, b01, b11;
                ldsm4(b00, b10, b01, b11, stb + bOff + jp * 1280 + k16 * 32);
                mma_f16(acc[0][2*jp],   a0[0], a1[0], a2[0], a3[0], b00, b10);
                mma_f16(acc[0][2*jp+1], a0[0], a1[0], a2[0], a3[0], b01, b11);
                mma_f16(acc[1][2*jp],   a0[1], a1[1], a2[1], a3[1], b00, b10);
                mma_f16(acc[1][2*jp+1], a0[1], a1[1], a2[1], a3[1], b01, b11);
            }
        }
    }
#undef PISSUE

    // Epilogue: unwindow + roll scatter (fp32 output)
#pragma unroll
    for (int mi = 0; mi < 2; mi++) {
#pragma unroll
        for (int h = 0; h < 2; h++) {
            int r  = rowBlock * 128 + wrb + mi * 16 + g + 8 * h;
            int pr = r & 63, wr = (r >> 6) & 1023, br = r >> 16;
            int hout = (((wr >> 5) << 3) + (pr >> 3) + SHIFT) & 255;
            int wout = ((wr & 31) << 3) + (pr & 7);
            size_t rowbase = (((size_t)br * HH + hout) * WW + wout) * OUTC;
#pragma unroll
            for (int nj = 0; nj < 8; nj++) {
                int n = colBlock * 128 + wcb + nj * 8 + t4 * 2;
                float2 v;
                v.x = acc[mi][nj][h * 2 + 0] + bo[n];
                v.y = acc[mi][nj][h * 2 + 1] + bo[n + 1];
                *reinterpret_cast<float2*>(&dst[rowbase + n]) = v;
            }
        }
    }
}

// ---------------------------------------------------------------------------
// Launch
// ---------------------------------------------------------------------------
extern "C" void kernel_launch(void* const* d_in, const int* in_sizes, int n_in,
                              void* d_out, int out_size)
{
    const float* emb1  = (const float*)d_in[0];
    const float* emb2  = (const float*)d_in[1];
    const float* Wqkv1 = (const float*)d_in[2];
    const float* bqkv1 = (const float*)d_in[3];
    const float* Wqkv2 = (const float*)d_in[4];
    const float* bqkv2 = (const float*)d_in[5];
    const float* rel1  = (const float*)d_in[6];
    const float* rel2  = (const float*)d_in[7];
    const float* Wo1   = (const float*)d_in[8];
    const float* bo1   = (const float*)d_in[9];
    const float* Wo2   = (const float*)d_in[10];
    const float* bo2   = (const float*)d_in[11];
    float* out = (float*)d_out;
    (void)in_sizes; (void)n_in; (void)out_size;

    cudaFuncSetAttribute(qkv_mma,  cudaFuncAttributeMaxDynamicSharedMemorySize, GEMM_SMEM);
    cudaFuncSetAttribute(proj_mma, cudaFuncAttributeMaxDynamicSharedMemorySize, GEMM_SMEM);

    bias_kernel<<<256, 256>>>(rel1, rel2);
    wpack_kernel<<<2048, 256>>>(Wqkv1, Wqkv2, Wo1, Wo2);
    embh_kernel<<<32768, 256>>>(emb1, emb2);

    dim3 gq(6, 1024, 2);
    qkv_mma<<<gq, 256, GEMM_SMEM>>>(bqkv1, bqkv2);

    dim3 ga(2048, 8, 2);
    attn_mma<<<ga, 128>>>();

    dim3 gp(2, 1024, 2);
    proj_mma<<<gp, 256, GEMM_SMEM>>>(bo1, bo2, out);
}